// round 1
// baseline (speedup 1.0000x reference)
#include <cuda_runtime.h>
#include <math.h>

#define CS   1024
#define NH   16
#define HD   64
#define SEQ  1024

// ---- scratch (device globals: allowed; no runtime allocation) ----
__device__ float g_q[SEQ * CS];
__device__ float g_k[SEQ * CS];
__device__ float g_v[SEQ * CS];
__device__ float g_g[SEQ * CS];
__device__ float g_o[SEQ * CS];
__device__ float g_z[(size_t)NH * SEQ * SEQ];   // logits -> probs (in place)

__constant__ float cWz[128 * 16];

// =====================================================================
// Kernel 1: batched projections.  mode 0: q = s@Wq^T + bq
//                                 mode 1: k = kin@Wk^T
//                                 mode 2: v = kin@Wv^T
//                                 mode 3: g = sigmoid(s@Wg^T)
// C[m,n] = sum_k A[m,k] * W[n,k].  BM=BN=128, BK=8, TM=TN=8.
// =====================================================================
__global__ __launch_bounds__(256, 2)
void proj_kernel(const float* __restrict__ s, const float* __restrict__ kin,
                 const float* __restrict__ Wq, const float* __restrict__ bq,
                 const float* __restrict__ Wk, const float* __restrict__ Wv,
                 const float* __restrict__ Wg)
{
    __shared__ float As[8][128];
    __shared__ float Bs[8][128];

    const float* A; const float* W; float* C;
    const float* bias = nullptr; bool sig = false;
    switch (blockIdx.z) {
        case 0:  A = s;   W = Wq; C = g_q; bias = bq; break;
        case 1:  A = kin; W = Wk; C = g_k; break;
        case 2:  A = kin; W = Wv; C = g_v; break;
        default: A = s;   W = Wg; C = g_g; sig = true; break;
    }

    const int tid = threadIdx.x;
    const int tx = tid & 15, ty = tid >> 4;
    const int m0 = blockIdx.y * 128, n0 = blockIdx.x * 128;
    const int lr = tid >> 1;            // 0..127
    const int lk = (tid & 1) << 2;      // 0 or 4

    const float* Ap = A + (m0 + lr) * CS + lk;
    const float* Wp = W + (n0 + lr) * CS + lk;

    float acc[8][8];
    #pragma unroll
    for (int i = 0; i < 8; i++)
        #pragma unroll
        for (int j = 0; j < 8; j++) acc[i][j] = 0.f;

    for (int k0 = 0; k0 < CS; k0 += 8) {
        float4 av = *(const float4*)(Ap + k0);
        float4 bv = *(const float4*)(Wp + k0);
        As[lk + 0][lr] = av.x; As[lk + 1][lr] = av.y;
        As[lk + 2][lr] = av.z; As[lk + 3][lr] = av.w;
        Bs[lk + 0][lr] = bv.x; Bs[lk + 1][lr] = bv.y;
        Bs[lk + 2][lr] = bv.z; Bs[lk + 3][lr] = bv.w;
        __syncthreads();
        #pragma unroll
        for (int kk = 0; kk < 8; kk++) {
            float a[8], b[8];
            *(float4*)&a[0] = *(const float4*)&As[kk][ty * 4];
            *(float4*)&a[4] = *(const float4*)&As[kk][64 + ty * 4];
            *(float4*)&b[0] = *(const float4*)&Bs[kk][tx * 4];
            *(float4*)&b[4] = *(const float4*)&Bs[kk][64 + tx * 4];
            #pragma unroll
            for (int i = 0; i < 8; i++)
                #pragma unroll
                for (int j = 0; j < 8; j++)
                    acc[i][j] += a[i] * b[j];
        }
        __syncthreads();
    }

    #pragma unroll
    for (int i = 0; i < 8; i++) {
        int m = m0 + ((i < 4) ? (ty * 4 + i) : (64 + ty * 4 + (i - 4)));
        #pragma unroll
        for (int jq = 0; jq < 2; jq++) {
            int n = n0 + jq * 64 + tx * 4;
            float vv[4];
            #pragma unroll
            for (int u = 0; u < 4; u++) {
                float x = acc[i][jq * 4 + u];
                if (bias) x += bias[n + u];
                if (sig)  x = 1.0f / (1.0f + expf(-x));
                vv[u] = x;
            }
            float4 o4 = make_float4(vv[0], vv[1], vv[2], vv[3]);
            *(float4*)&C[m * CS + n] = o4;
        }
    }
}

// =====================================================================
// Kernel 2: z[h,i,j] = sum_c bias[i,j,c] * Wz[c,h]  + (1-mask[j])*(-1e6)
// One thread per (i,j) pair; bias staged through SMEM in c-chunks of 32;
// Wz from __constant__ (loop-uniform -> broadcast, no LDS traffic).
// =====================================================================
__global__ __launch_bounds__(256)
void zbias_kernel(const float* __restrict__ bias, const float* __restrict__ mask)
{
    __shared__ float sb[256][33];   // pad 33: conflict-free scalar reads
    const int tid = threadIdx.x;
    const long p0 = (long)blockIdx.x * 256;

    float acc[16];
    #pragma unroll
    for (int h = 0; h < 16; h++) acc[h] = 0.f;

    for (int cb = 0; cb < 4; cb++) {
        __syncthreads();
        // stage 256 pairs x 32 c  (coalesced float4 global loads)
        #pragma unroll
        for (int r = 0; r < 8; r++) {
            int f    = tid + r * 256;     // 0..2047
            int pair = f >> 3;            // 0..255
            int cq   = f & 7;             // 0..7
            float4 v = *(const float4*)&bias[(p0 + pair) * 128 + cb * 32 + cq * 4];
            sb[pair][cq * 4 + 0] = v.x; sb[pair][cq * 4 + 1] = v.y;
            sb[pair][cq * 4 + 2] = v.z; sb[pair][cq * 4 + 3] = v.w;
        }
        __syncthreads();
        #pragma unroll
        for (int c = 0; c < 32; c++) {
            float bvf = sb[tid][c];
            int cg = cb * 32 + c;
            #pragma unroll
            for (int h = 0; h < 16; h++)
                acc[h] += bvf * cWz[cg * 16 + h];
        }
    }

    const long p = p0 + tid;
    const int j = (int)(p & (SEQ - 1));
    const float madd = (1.0f - mask[j]) * (-1000000.0f);
    #pragma unroll
    for (int h = 0; h < 16; h++)
        g_z[((long)h << 20) + p] = acc[h] + madd;
}

// =====================================================================
// Kernel 3: logits (in place into g_z):  z[h,i,j] += (q_h . k_h)/8
// Per head GEMM  M=N=1024, K=64.  BM=BN=128, BK=8, TM=TN=8.
// =====================================================================
__global__ __launch_bounds__(256, 2)
void logits_kernel()
{
    __shared__ float Qs[8][128];
    __shared__ float Ks[8][128];

    const int h  = blockIdx.z;
    const int tid = threadIdx.x;
    const int tx = tid & 15, ty = tid >> 4;
    const int i0 = blockIdx.y * 128, j0 = blockIdx.x * 128;
    const int lr = tid >> 1;
    const int lk = (tid & 1) << 2;

    const float* Qp = g_q + (i0 + lr) * CS + h * HD + lk;
    const float* Kp = g_k + (j0 + lr) * CS + h * HD + lk;

    float acc[8][8];
    #pragma unroll
    for (int i = 0; i < 8; i++)
        #pragma unroll
        for (int j = 0; j < 8; j++) acc[i][j] = 0.f;

    for (int k0 = 0; k0 < HD; k0 += 8) {
        float4 av = *(const float4*)(Qp + k0);
        float4 bv = *(const float4*)(Kp + k0);
        Qs[lk + 0][lr] = av.x; Qs[lk + 1][lr] = av.y;
        Qs[lk + 2][lr] = av.z; Qs[lk + 3][lr] = av.w;
        Ks[lk + 0][lr] = bv.x; Ks[lk + 1][lr] = bv.y;
        Ks[lk + 2][lr] = bv.z; Ks[lk + 3][lr] = bv.w;
        __syncthreads();
        #pragma unroll
        for (int kk = 0; kk < 8; kk++) {
            float a[8], b[8];
            *(float4*)&a[0] = *(const float4*)&Qs[kk][ty * 4];
            *(float4*)&a[4] = *(const float4*)&Qs[kk][64 + ty * 4];
            *(float4*)&b[0] = *(const float4*)&Ks[kk][tx * 4];
            *(float4*)&b[4] = *(const float4*)&Ks[kk][64 + tx * 4];
            #pragma unroll
            for (int i = 0; i < 8; i++)
                #pragma unroll
                for (int j = 0; j < 8; j++)
                    acc[i][j] += a[i] * b[j];
        }
        __syncthreads();
    }

    float* Z = g_z + ((long)h << 20);
    #pragma unroll
    for (int i = 0; i < 8; i++) {
        int m = i0 + ((i < 4) ? (ty * 4 + i) : (64 + ty * 4 + (i - 4)));
        #pragma unroll
        for (int jq = 0; jq < 2; jq++) {
            int n = j0 + jq * 64 + tx * 4;
            float4 zv = *(float4*)&Z[m * SEQ + n];
            zv.x += 0.125f * acc[i][jq * 4 + 0];
            zv.y += 0.125f * acc[i][jq * 4 + 1];
            zv.z += 0.125f * acc[i][jq * 4 + 2];
            zv.w += 0.125f * acc[i][jq * 4 + 3];
            *(float4*)&Z[m * SEQ + n] = zv;
        }
    }
}

// =====================================================================
// Kernel 4: row softmax over j (1024) in place.  One block per (h,i).
// =====================================================================
__global__ __launch_bounds__(256)
void softmax_kernel()
{
    __shared__ float red[8];
    const long row = blockIdx.x;            // h*1024 + i
    float* Z = g_z + row * SEQ;
    const int tid = threadIdx.x;

    float4 v = *(float4*)&Z[tid * 4];
    float m = fmaxf(fmaxf(v.x, v.y), fmaxf(v.z, v.w));
    #pragma unroll
    for (int o = 16; o; o >>= 1) m = fmaxf(m, __shfl_xor_sync(0xffffffffu, m, o));
    if ((tid & 31) == 0) red[tid >> 5] = m;
    __syncthreads();
    float m2 = red[0];
    #pragma unroll
    for (int w = 1; w < 8; w++) m2 = fmaxf(m2, red[w]);
    __syncthreads();

    float e0 = __expf(v.x - m2), e1 = __expf(v.y - m2);
    float e2 = __expf(v.z - m2), e3 = __expf(v.w - m2);
    float s = (e0 + e1) + (e2 + e3);
    #pragma unroll
    for (int o = 16; o; o >>= 1) s += __shfl_xor_sync(0xffffffffu, s, o);
    if ((tid & 31) == 0) red[tid >> 5] = s;
    __syncthreads();
    float tot = 0.f;
    #pragma unroll
    for (int w = 0; w < 8; w++) tot += red[w];
    float inv = 1.0f / tot;

    float4 o4 = make_float4(e0 * inv, e1 * inv, e2 * inv, e3 * inv);
    *(float4*)&Z[tid * 4] = o4;
}

// =====================================================================
// Kernel 5: o[i, h*64+d] = sum_j P[h,i,j] * v[j, h*64+d]
// Per head GEMM M=1024, N=64, K=1024.  BM=BN=64, BK=8, TM=TN=4.
// =====================================================================
__global__ __launch_bounds__(256, 2)
void attnv_kernel()
{
    __shared__ float Ps[8][64];
    __shared__ float Vs[8][64];

    const int h  = blockIdx.y;
    const int i0 = blockIdx.x * 64;
    const int tid = threadIdx.x;
    const int tx = tid & 15, ty = tid >> 4;
    const float* P = g_z + ((long)h << 20);

    float acc[4][4];
    #pragma unroll
    for (int i = 0; i < 4; i++)
        #pragma unroll
        for (int j = 0; j < 4; j++) acc[i][j] = 0.f;

    for (int k0 = 0; k0 < SEQ; k0 += 8) {
        if (tid < 128) {
            int r = tid >> 1, lk = (tid & 1) << 2;
            float4 pv = *(const float4*)&P[(i0 + r) * SEQ + k0 + lk];
            Ps[lk + 0][r] = pv.x; Ps[lk + 1][r] = pv.y;
            Ps[lk + 2][r] = pv.z; Ps[lk + 3][r] = pv.w;
        } else {
            int t = tid - 128;
            int r = t >> 4, dq = (t & 15) << 2;
            float4 vv = *(const float4*)&g_v[(k0 + r) * CS + h * HD + dq];
            Vs[r][dq + 0] = vv.x; Vs[r][dq + 1] = vv.y;
            Vs[r][dq + 2] = vv.z; Vs[r][dq + 3] = vv.w;
        }
        __syncthreads();
        #pragma unroll
        for (int kk = 0; kk < 8; kk++) {
            float a[4], b[4];
            *(float4*)a = *(const float4*)&Ps[kk][ty * 4];
            *(float4*)b = *(const float4*)&Vs[kk][tx * 4];
            #pragma unroll
            for (int i = 0; i < 4; i++)
                #pragma unroll
                for (int j = 0; j < 4; j++)
                    acc[i][j] += a[i] * b[j];
        }
        __syncthreads();
    }

    #pragma unroll
    for (int i = 0; i < 4; i++) {
        int m = i0 + ty * 4 + i;
        float4 o4 = make_float4(acc[i][0], acc[i][1], acc[i][2], acc[i][3]);
        *(float4*)&g_o[m * CS + h * HD + tx * 4] = o4;
    }
}

// =====================================================================
// Kernel 6: out[i,n] = sum_c (g[i,c]*o[i,c]) * Wo[n,c]
// BM=BN=64, BK=8, TM=TN=4; gate fused into the A-tile load.
// =====================================================================
__global__ __launch_bounds__(256, 2)
void out_kernel(const float* __restrict__ Wo, float* __restrict__ out)
{
    __shared__ float As[8][64];
    __shared__ float Bs[8][64];

    const int i0 = blockIdx.y * 64, n0 = blockIdx.x * 64;
    const int tid = threadIdx.x;
    const int tx = tid & 15, ty = tid >> 4;

    float acc[4][4];
    #pragma unroll
    for (int i = 0; i < 4; i++)
        #pragma unroll
        for (int j = 0; j < 4; j++) acc[i][j] = 0.f;

    for (int k0 = 0; k0 < CS; k0 += 8) {
        if (tid < 128) {
            int r = tid >> 1, lk = (tid & 1) << 2;
            float4 ov = *(const float4*)&g_o[(i0 + r) * CS + k0 + lk];
            float4 gv = *(const float4*)&g_g[(i0 + r) * CS + k0 + lk];
            As[lk + 0][r] = ov.x * gv.x; As[lk + 1][r] = ov.y * gv.y;
            As[lk + 2][r] = ov.z * gv.z; As[lk + 3][r] = ov.w * gv.w;
        } else {
            int t = tid - 128;
            int r = t >> 1, lk = (t & 1) << 2;
            float4 wv = *(const float4*)&Wo[(n0 + r) * CS + k0 + lk];
            Bs[lk + 0][r] = wv.x; Bs[lk + 1][r] = wv.y;
            Bs[lk + 2][r] = wv.z; Bs[lk + 3][r] = wv.w;
        }
        __syncthreads();
        #pragma unroll
        for (int kk = 0; kk < 8; kk++) {
            float a[4], b[4];
            *(float4*)a = *(const float4*)&As[kk][ty * 4];
            *(float4*)b = *(const float4*)&Bs[kk][tx * 4];
            #pragma unroll
            for (int i = 0; i < 4; i++)
                #pragma unroll
                for (int j = 0; j < 4; j++)
                    acc[i][j] += a[i] * b[j];
        }
        __syncthreads();
    }

    #pragma unroll
    for (int i = 0; i < 4; i++) {
        int m = i0 + ty * 4 + i;
        float4 o4 = make_float4(acc[i][0], acc[i][1], acc[i][2], acc[i][3]);
        *(float4*)&out[m * CS + n0 + tx * 4] = o4;
    }
}

// =====================================================================
extern "C" void kernel_launch(void* const* d_in, const int* in_sizes, int n_in,
                              void* d_out, int out_size)
{
    const float* s    = (const float*)d_in[0];
    const float* kin  = (const float*)d_in[1];
    const float* mask = (const float*)d_in[2];
    const float* bias = (const float*)d_in[3];
    const float* Wq   = (const float*)d_in[4];
    const float* bq   = (const float*)d_in[5];
    const float* Wk   = (const float*)d_in[6];
    const float* Wv   = (const float*)d_in[7];
    const float* Wg   = (const float*)d_in[8];
    const float* Wo   = (const float*)d_in[9];
    const float* Wz   = (const float*)d_in[10];
    // d_in[11] = multiplicity (always 1 here)
    float* out = (float*)d_out;

    cudaMemcpyToSymbolAsync(cWz, Wz, 128 * 16 * sizeof(float), 0,
                            cudaMemcpyDeviceToDevice);

    proj_kernel <<<dim3(8, 8, 4),  256>>>(s, kin, Wq, bq, Wk, Wv, Wg);
    zbias_kernel<<<4096,           256>>>(bias, mask);
    logits_kernel<<<dim3(8, 8, 16), 256>>>();
    softmax_kernel<<<NH * SEQ,     256>>>();
    attnv_kernel<<<dim3(16, 16),   256>>>();
    out_kernel  <<<dim3(16, 16),   256>>>(Wo, out);
}

// round 2
// speedup vs baseline: 1.3807x; 1.3807x over previous
#include <cuda_runtime.h>
#include <cuda_bf16.h>
#include <math.h>

#define CS   1024
#define NH   16
#define HD   64
#define SEQ  1024

// ---------------- scratch (device globals) ----------------
__device__ float g_q[SEQ * CS];
__device__ float g_k[SEQ * CS];
__device__ float g_v[SEQ * CS];
__device__ float g_g[SEQ * CS];
__device__ float g_o[SEQ * CS];
__device__ float g_z[(size_t)NH * SEQ * SEQ];
__constant__ float cWz[128 * 16];

// bf16 hi/lo split buffers (for bf16x3 tensor-core GEMMs)
__device__ __align__(16) __nv_bfloat16 b_s_h[SEQ*CS],  b_s_l[SEQ*CS];
__device__ __align__(16) __nv_bfloat16 b_k_h[SEQ*CS],  b_k_l[SEQ*CS];
__device__ __align__(16) __nv_bfloat16 b_Wq_h[CS*CS],  b_Wq_l[CS*CS];
__device__ __align__(16) __nv_bfloat16 b_Wk_h[CS*CS],  b_Wk_l[CS*CS];
__device__ __align__(16) __nv_bfloat16 b_Wv_h[CS*CS],  b_Wv_l[CS*CS];
__device__ __align__(16) __nv_bfloat16 b_Wg_h[CS*CS],  b_Wg_l[CS*CS];
__device__ __align__(16) __nv_bfloat16 b_Wo_h[CS*CS],  b_Wo_l[CS*CS];
__device__ __align__(16) __nv_bfloat16 b_a_h[SEQ*CS],  b_a_l[SEQ*CS];

// ---------------- mma / ldmatrix primitives ----------------
__device__ __forceinline__ void mma_bf16(float d[4], const unsigned a[4], const unsigned b[2]) {
    asm volatile(
        "mma.sync.aligned.m16n8k16.row.col.f32.bf16.bf16.f32 "
        "{%0,%1,%2,%3},{%4,%5,%6,%7},{%8,%9},{%0,%1,%2,%3};\n"
        : "+f"(d[0]), "+f"(d[1]), "+f"(d[2]), "+f"(d[3])
        : "r"(a[0]), "r"(a[1]), "r"(a[2]), "r"(a[3]), "r"(b[0]), "r"(b[1]));
}
__device__ __forceinline__ void ldsm4(unsigned r[4], unsigned addr) {
    asm volatile("ldmatrix.sync.aligned.m8n8.x4.shared.b16 {%0,%1,%2,%3}, [%4];\n"
                 : "=r"(r[0]), "=r"(r[1]), "=r"(r[2]), "=r"(r[3]) : "r"(addr));
}
__device__ __forceinline__ void ldsm2(unsigned r[2], unsigned addr) {
    asm volatile("ldmatrix.sync.aligned.m8n8.x2.shared.b16 {%0,%1}, [%2];\n"
                 : "=r"(r[0]), "=r"(r[1]) : "r"(addr));
}
__device__ __forceinline__ unsigned smem_u32(const void* p) {
    return (unsigned)__cvta_generic_to_shared(p);
}

// ---------------- fp32 -> bf16 hi/lo splitting ----------------
__device__ __forceinline__ void split1(float x, __nv_bfloat16& h, __nv_bfloat16& l) {
    h = __float2bfloat16_rn(x);
    l = __float2bfloat16_rn(x - __bfloat162float(h));
}
__device__ __forceinline__ void split4_store(float4 v, __nv_bfloat16* ph, __nv_bfloat16* pl) {
    __nv_bfloat16 h0,h1,h2,h3,l0,l1,l2,l3;
    split1(v.x,h0,l0); split1(v.y,h1,l1); split1(v.z,h2,l2); split1(v.w,h3,l3);
    __nv_bfloat162 hh0 = __halves2bfloat162(h0,h1), hh1 = __halves2bfloat162(h2,h3);
    __nv_bfloat162 ll0 = __halves2bfloat162(l0,l1), ll1 = __halves2bfloat162(l2,l3);
    uint2 hu; hu.x = *(unsigned*)&hh0; hu.y = *(unsigned*)&hh1;
    uint2 lu; lu.x = *(unsigned*)&ll0; lu.y = *(unsigned*)&ll1;
    *(uint2*)ph = hu; *(uint2*)pl = lu;
}

// Kernel S: split the 7 fp32 source matrices into bf16 hi/lo
__global__ __launch_bounds__(256)
void split_kernel(const float* __restrict__ s,  const float* __restrict__ kin,
                  const float* __restrict__ Wq, const float* __restrict__ Wk,
                  const float* __restrict__ Wv, const float* __restrict__ Wg,
                  const float* __restrict__ Wo)
{
    const float* src; __nv_bfloat16 *dh, *dl;
    switch (blockIdx.y) {
        case 0:  src = s;   dh = b_s_h;  dl = b_s_l;  break;
        case 1:  src = kin; dh = b_k_h;  dl = b_k_l;  break;
        case 2:  src = Wq;  dh = b_Wq_h; dl = b_Wq_l; break;
        case 3:  src = Wk;  dh = b_Wk_h; dl = b_Wk_l; break;
        case 4:  src = Wv;  dh = b_Wv_h; dl = b_Wv_l; break;
        case 5:  src = Wg;  dh = b_Wg_h; dl = b_Wg_l; break;
        default: src = Wo;  dh = b_Wo_h; dl = b_Wo_l; break;
    }
    int i = (blockIdx.x * 256 + threadIdx.x) * 4;
    float4 v = *(const float4*)(src + i);
    split4_store(v, dh + i, dl + i);
}

// Kernel G: a = g * o, split to bf16 hi/lo (feeds out_mma)
__global__ __launch_bounds__(256)
void gatesplit_kernel()
{
    int i = (blockIdx.x * 256 + threadIdx.x) * 4;
    float4 gv = *(const float4*)&g_g[i];
    float4 ov = *(const float4*)&g_o[i];
    float4 a  = make_float4(gv.x*ov.x, gv.y*ov.y, gv.z*ov.z, gv.w*ov.w);
    split4_store(a, b_a_h + i, b_a_l + i);
}

// ---------------- bf16x3 tensor-core GEMM core ----------------
// C[m,n] = sum_k A[m,k]*B[n,k]  (both operands k-contiguous, K=1024)
// BM=BN=128, BK=32.  8 warps in 2x4; warp tile 64x32; m16n8k16 mma, 3 terms.
#define LDT 40   // smem row stride in halves (32 + 8 pad: LDSM conflict-free)

__device__ __forceinline__ void mma_core(
    const __nv_bfloat16* __restrict__ Ah, const __nv_bfloat16* __restrict__ Al,
    const __nv_bfloat16* __restrict__ Bh, const __nv_bfloat16* __restrict__ Bl,
    int m0, int n0, float acc[4][4][4])
{
    __shared__ __nv_bfloat16 sAh[128*LDT], sAl[128*LDT], sBh[128*LDT], sBl[128*LDT];

    const int tid  = threadIdx.x;
    const int lane = tid & 31;
    const int warp = tid >> 5;
    const int wm   = warp >> 2;      // 0..1
    const int wn   = warp & 3;       // 0..3

    #pragma unroll
    for (int mt = 0; mt < 4; mt++)
        #pragma unroll
        for (int nt = 0; nt < 4; nt++)
            #pragma unroll
            for (int u = 0; u < 4; u++) acc[mt][nt][u] = 0.f;

    // per-thread global-load slots: 2 x 16B per matrix per iter
    int c0i = tid, c1i = tid + 256;
    int r0 = c0i >> 2, s0 = (c0i & 3) * 8;
    int r1 = c1i >> 2, s1 = (c1i & 3) * 8;

    uint4 pAh0, pAh1, pAl0, pAl1, pBh0, pBh1, pBl0, pBl1;
    {
        size_t a0 = (size_t)(m0 + r0) * CS + s0, a1 = (size_t)(m0 + r1) * CS + s1;
        size_t b0 = (size_t)(n0 + r0) * CS + s0, b1 = (size_t)(n0 + r1) * CS + s1;
        pAh0 = *(const uint4*)(Ah + a0); pAh1 = *(const uint4*)(Ah + a1);
        pAl0 = *(const uint4*)(Al + a0); pAl1 = *(const uint4*)(Al + a1);
        pBh0 = *(const uint4*)(Bh + b0); pBh1 = *(const uint4*)(Bh + b1);
        pBl0 = *(const uint4*)(Bl + b0); pBl1 = *(const uint4*)(Bl + b1);
    }

    // LDSM base addresses (per-lane row pointers)
    const int amat = lane >> 3, arow = lane & 7;
    const int a_r  = wm * 64 + (amat & 1) * 8 + arow;        // + mt*16
    const int a_c  = (amat >> 1) * 8;                        // + ks
    const int b_r  = wn * 32 + (arow);                       // + nt*8
    const int b_c  = ((lane >> 3) & 1) * 8;                  // + ks

    const unsigned uAh = smem_u32(sAh), uAl = smem_u32(sAl);
    const unsigned uBh = smem_u32(sBh), uBl = smem_u32(sBl);

    for (int k0 = 0; k0 < CS; k0 += 32) {
        // commit prefetched tiles to smem
        *(uint4*)&sAh[r0*LDT + s0] = pAh0; *(uint4*)&sAh[r1*LDT + s1] = pAh1;
        *(uint4*)&sAl[r0*LDT + s0] = pAl0; *(uint4*)&sAl[r1*LDT + s1] = pAl1;
        *(uint4*)&sBh[r0*LDT + s0] = pBh0; *(uint4*)&sBh[r1*LDT + s1] = pBh1;
        *(uint4*)&sBl[r0*LDT + s0] = pBl0; *(uint4*)&sBl[r1*LDT + s1] = pBl1;
        __syncthreads();

        if (k0 + 32 < CS) {   // prefetch next iter (overlaps with mma below)
            int kn = k0 + 32;
            size_t a0 = (size_t)(m0 + r0) * CS + kn + s0, a1 = (size_t)(m0 + r1) * CS + kn + s1;
            size_t b0 = (size_t)(n0 + r0) * CS + kn + s0, b1 = (size_t)(n0 + r1) * CS + kn + s1;
            pAh0 = *(const uint4*)(Ah + a0); pAh1 = *(const uint4*)(Ah + a1);
            pAl0 = *(const uint4*)(Al + a0); pAl1 = *(const uint4*)(Al + a1);
            pBh0 = *(const uint4*)(Bh + b0); pBh1 = *(const uint4*)(Bh + b1);
            pBl0 = *(const uint4*)(Bl + b0); pBl1 = *(const uint4*)(Bl + b1);
        }

        #pragma unroll
        for (int ks = 0; ks < 32; ks += 16) {
            unsigned afh[4][4], afl[4][4], bfh[4][2], bfl[4][2];
            #pragma unroll
            for (int mt = 0; mt < 4; mt++) {
                unsigned off = ((a_r + mt*16) * LDT + ks + a_c) * 2;
                ldsm4(afh[mt], uAh + off);
                ldsm4(afl[mt], uAl + off);
            }
            #pragma unroll
            for (int nt = 0; nt < 4; nt++) {
                unsigned off = ((b_r + nt*8) * LDT + ks + b_c) * 2;
                ldsm2(bfh[nt], uBh + off);
                ldsm2(bfl[nt], uBl + off);
            }
            #pragma unroll
            for (int mt = 0; mt < 4; mt++)
                #pragma unroll
                for (int nt = 0; nt < 4; nt++) {
                    mma_bf16(acc[mt][nt], afh[mt], bfh[nt]);   // hi*hi
                    mma_bf16(acc[mt][nt], afh[mt], bfl[nt]);   // hi*lo
                    mma_bf16(acc[mt][nt], afl[mt], bfh[nt]);   // lo*hi
                }
        }
        __syncthreads();
    }
}

// Kernel 1: projections on tensor cores.  z: 0=q(+bq) 1=k 2=v 3=g(sigmoid)
__global__ __launch_bounds__(256)
void proj_mma(const float* __restrict__ bq)
{
    const __nv_bfloat16 *Ah, *Al, *Bh, *Bl; float* C;
    const float* bias = nullptr; bool sig = false;
    switch (blockIdx.z) {
        case 0:  Ah=b_s_h; Al=b_s_l; Bh=b_Wq_h; Bl=b_Wq_l; C=g_q; bias=bq; break;
        case 1:  Ah=b_k_h; Al=b_k_l; Bh=b_Wk_h; Bl=b_Wk_l; C=g_k; break;
        case 2:  Ah=b_k_h; Al=b_k_l; Bh=b_Wv_h; Bl=b_Wv_l; C=g_v; break;
        default: Ah=b_s_h; Al=b_s_l; Bh=b_Wg_h; Bl=b_Wg_l; C=g_g; sig=true; break;
    }
    const int m0 = blockIdx.y * 128, n0 = blockIdx.x * 128;
    float acc[4][4][4];
    mma_core(Ah, Al, Bh, Bl, m0, n0, acc);

    const int lane = threadIdx.x & 31, warp = threadIdx.x >> 5;
    const int wm = warp >> 2, wn = warp & 3;
    const int lr = lane >> 2, lc = (lane & 3) * 2;
    #pragma unroll
    for (int mt = 0; mt < 4; mt++)
        #pragma unroll
        for (int nt = 0; nt < 4; nt++) {
            int row = m0 + wm*64 + mt*16 + lr;
            int col = n0 + wn*32 + nt*8 + lc;
            float v0 = acc[mt][nt][0], v1 = acc[mt][nt][1];
            float v2 = acc[mt][nt][2], v3 = acc[mt][nt][3];
            if (bias) { float b0_ = bias[col], b1_ = bias[col+1];
                        v0 += b0_; v1 += b1_; v2 += b0_; v3 += b1_; }
            if (sig) {
                v0 = 1.0f/(1.0f+__expf(-v0)); v1 = 1.0f/(1.0f+__expf(-v1));
                v2 = 1.0f/(1.0f+__expf(-v2)); v3 = 1.0f/(1.0f+__expf(-v3));
            }
            *(float2*)&C[(size_t)row*CS + col]     = make_float2(v0, v1);
            *(float2*)&C[(size_t)(row+8)*CS + col] = make_float2(v2, v3);
        }
}

// Kernel 6: out = (g*o) @ Wo^T on tensor cores
__global__ __launch_bounds__(256)
void out_mma(float* __restrict__ out)
{
    const int m0 = blockIdx.y * 128, n0 = blockIdx.x * 128;
    float acc[4][4][4];
    mma_core(b_a_h, b_a_l, b_Wo_h, b_Wo_l, m0, n0, acc);

    const int lane = threadIdx.x & 31, warp = threadIdx.x >> 5;
    const int wm = warp >> 2, wn = warp & 3;
    const int lr = lane >> 2, lc = (lane & 3) * 2;
    #pragma unroll
    for (int mt = 0; mt < 4; mt++)
        #pragma unroll
        for (int nt = 0; nt < 4; nt++) {
            int row = m0 + wm*64 + mt*16 + lr;
            int col = n0 + wn*32 + nt*8 + lc;
            *(float2*)&out[(size_t)row*CS + col]     = make_float2(acc[mt][nt][0], acc[mt][nt][1]);
            *(float2*)&out[(size_t)(row+8)*CS + col] = make_float2(acc[mt][nt][2], acc[mt][nt][3]);
        }
}

// ---------------- unchanged fp32 attention stages (verified R1) ----------------
__global__ __launch_bounds__(256)
void zbias_kernel(const float* __restrict__ bias, const float* __restrict__ mask)
{
    __shared__ float sb[256][33];
    const int tid = threadIdx.x;
    const long p0 = (long)blockIdx.x * 256;

    float acc[16];
    #pragma unroll
    for (int h = 0; h < 16; h++) acc[h] = 0.f;

    for (int cb = 0; cb < 4; cb++) {
        __syncthreads();
        #pragma unroll
        for (int r = 0; r < 8; r++) {
            int f = tid + r * 256;
            int pair = f >> 3, cq = f & 7;
            float4 v = *(const float4*)&bias[(p0 + pair) * 128 + cb * 32 + cq * 4];
            sb[pair][cq*4+0] = v.x; sb[pair][cq*4+1] = v.y;
            sb[pair][cq*4+2] = v.z; sb[pair][cq*4+3] = v.w;
        }
        __syncthreads();
        #pragma unroll
        for (int c = 0; c < 32; c++) {
            float bvf = sb[tid][c];
            int cg = cb * 32 + c;
            #pragma unroll
            for (int h = 0; h < 16; h++)
                acc[h] += bvf * cWz[cg * 16 + h];
        }
    }
    const long p = p0 + tid;
    const int j = (int)(p & (SEQ - 1));
    const float madd = (1.0f - mask[j]) * (-1000000.0f);
    #pragma unroll
    for (int h = 0; h < 16; h++)
        g_z[((long)h << 20) + p] = acc[h] + madd;
}

__global__ __launch_bounds__(256, 2)
void logits_kernel()
{
    __shared__ float Qs[8][128];
    __shared__ float Ks[8][128];

    const int h = blockIdx.z;
    const int tid = threadIdx.x;
    const int tx = tid & 15, ty = tid >> 4;
    const int i0 = blockIdx.y * 128, j0 = blockIdx.x * 128;
    const int lr = tid >> 1, lk = (tid & 1) << 2;

    const float* Qp = g_q + (i0 + lr) * CS + h * HD + lk;
    const float* Kp = g_k + (j0 + lr) * CS + h * HD + lk;

    float acc[8][8];
    #pragma unroll
    for (int i = 0; i < 8; i++)
        #pragma unroll
        for (int j = 0; j < 8; j++) acc[i][j] = 0.f;

    for (int k0 = 0; k0 < HD; k0 += 8) {
        float4 av = *(const float4*)(Qp + k0);
        float4 bv = *(const float4*)(Kp + k0);
        Qs[lk+0][lr] = av.x; Qs[lk+1][lr] = av.y; Qs[lk+2][lr] = av.z; Qs[lk+3][lr] = av.w;
        Ks[lk+0][lr] = bv.x; Ks[lk+1][lr] = bv.y; Ks[lk+2][lr] = bv.z; Ks[lk+3][lr] = bv.w;
        __syncthreads();
        #pragma unroll
        for (int kk = 0; kk < 8; kk++) {
            float a[8], b[8];
            *(float4*)&a[0] = *(const float4*)&Qs[kk][ty*4];
            *(float4*)&a[4] = *(const float4*)&Qs[kk][64 + ty*4];
            *(float4*)&b[0] = *(const float4*)&Ks[kk][tx*4];
            *(float4*)&b[4] = *(const float4*)&Ks[kk][64 + tx*4];
            #pragma unroll
            for (int i = 0; i < 8; i++)
                #pragma unroll
                for (int j = 0; j < 8; j++)
                    acc[i][j] += a[i] * b[j];
        }
        __syncthreads();
    }

    float* Z = g_z + ((long)h << 20);
    #pragma unroll
    for (int i = 0; i < 8; i++) {
        int m = i0 + ((i < 4) ? (ty*4 + i) : (64 + ty*4 + (i - 4)));
        #pragma unroll
        for (int jq = 0; jq < 2; jq++) {
            int n = j0 + jq*64 + tx*4;
            float4 zv = *(float4*)&Z[m * SEQ + n];
            zv.x += 0.125f * acc[i][jq*4+0];
            zv.y += 0.125f * acc[i][jq*4+1];
            zv.z += 0.125f * acc[i][jq*4+2];
            zv.w += 0.125f * acc[i][jq*4+3];
            *(float4*)&Z[m * SEQ + n] = zv;
        }
    }
}

__global__ __launch_bounds__(256)
void softmax_kernel()
{
    __shared__ float red[8];
    const long row = blockIdx.x;
    float* Z = g_z + row * SEQ;
    const int tid = threadIdx.x;

    float4 v = *(float4*)&Z[tid * 4];
    float m = fmaxf(fmaxf(v.x, v.y), fmaxf(v.z, v.w));
    #pragma unroll
    for (int o = 16; o; o >>= 1) m = fmaxf(m, __shfl_xor_sync(0xffffffffu, m, o));
    if ((tid & 31) == 0) red[tid >> 5] = m;
    __syncthreads();
    float m2 = red[0];
    #pragma unroll
    for (int w = 1; w < 8; w++) m2 = fmaxf(m2, red[w]);
    __syncthreads();

    float e0 = __expf(v.x - m2), e1 = __expf(v.y - m2);
    float e2 = __expf(v.z - m2), e3 = __expf(v.w - m2);
    float s = (e0 + e1) + (e2 + e3);
    #pragma unroll
    for (int o = 16; o; o >>= 1) s += __shfl_xor_sync(0xffffffffu, s, o);
    if ((tid & 31) == 0) red[tid >> 5] = s;
    __syncthreads();
    float tot = 0.f;
    #pragma unroll
    for (int w = 0; w < 8; w++) tot += red[w];
    float inv = 1.0f / tot;

    *(float4*)&Z[tid * 4] = make_float4(e0*inv, e1*inv, e2*inv, e3*inv);
}

__global__ __launch_bounds__(256, 2)
void attnv_kernel()
{
    __shared__ float Ps[8][64];
    __shared__ float Vs[8][64];

    const int h = blockIdx.y;
    const int i0 = blockIdx.x * 64;
    const int tid = threadIdx.x;
    const int tx = tid & 15, ty = tid >> 4;
    const float* P = g_z + ((long)h << 20);

    float acc[4][4];
    #pragma unroll
    for (int i = 0; i < 4; i++)
        #pragma unroll
        for (int j = 0; j < 4; j++) acc[i][j] = 0.f;

    for (int k0 = 0; k0 < SEQ; k0 += 8) {
        if (tid < 128) {
            int r = tid >> 1, lk = (tid & 1) << 2;
            float4 pv = *(const float4*)&P[(i0 + r) * SEQ + k0 + lk];
            Ps[lk+0][r] = pv.x; Ps[lk+1][r] = pv.y; Ps[lk+2][r] = pv.z; Ps[lk+3][r] = pv.w;
        } else {
            int t = tid - 128;
            int r = t >> 4, dq = (t & 15) << 2;
            float4 vv = *(const float4*)&g_v[(k0 + r) * CS + h * HD + dq];
            Vs[r][dq+0] = vv.x; Vs[r][dq+1] = vv.y; Vs[r][dq+2] = vv.z; Vs[r][dq+3] = vv.w;
        }
        __syncthreads();
        #pragma unroll
        for (int kk = 0; kk < 8; kk++) {
            float a[4], b[4];
            *(float4*)a = *(const float4*)&Ps[kk][ty*4];
            *(float4*)b = *(const float4*)&Vs[kk][tx*4];
            #pragma unroll
            for (int i = 0; i < 4; i++)
                #pragma unroll
                for (int j = 0; j < 4; j++)
                    acc[i][j] += a[i] * b[j];
        }
        __syncthreads();
    }

    #pragma unroll
    for (int i = 0; i < 4; i++) {
        int m = i0 + ty*4 + i;
        *(float4*)&g_o[m * CS + h * HD + tx*4] =
            make_float4(acc[i][0], acc[i][1], acc[i][2], acc[i][3]);
    }
}

// =====================================================================
extern "C" void kernel_launch(void* const* d_in, const int* in_sizes, int n_in,
                              void* d_out, int out_size)
{
    const float* s    = (const float*)d_in[0];
    const float* kin  = (const float*)d_in[1];
    const float* mask = (const float*)d_in[2];
    const float* bias = (const float*)d_in[3];
    const float* Wq   = (const float*)d_in[4];
    const float* bq   = (const float*)d_in[5];
    const float* Wk   = (const float*)d_in[6];
    const float* Wv   = (const float*)d_in[7];
    const float* Wg   = (const float*)d_in[8];
    const float* Wo   = (const float*)d_in[9];
    const float* Wz   = (const float*)d_in[10];
    float* out = (float*)d_out;

    cudaMemcpyToSymbolAsync(cWz, Wz, 128 * 16 * sizeof(float), 0,
                            cudaMemcpyDeviceToDevice);

    split_kernel<<<dim3(1024, 7), 256>>>(s, kin, Wq, Wk, Wv, Wg, Wo);
    proj_mma    <<<dim3(8, 8, 4),  256>>>(bq);
    zbias_kernel<<<4096,           256>>>(bias, mask);
    logits_kernel<<<dim3(8, 8, 16), 256>>>();
    softmax_kernel<<<NH * SEQ,     256>>>();
    attnv_kernel<<<dim3(16, 16),   256>>>();
    gatesplit_kernel<<<1024,       256>>>();
    out_mma     <<<dim3(8, 8),     256>>>(out);
}

// round 3
// speedup vs baseline: 1.8902x; 1.3690x over previous
#include <cuda_runtime.h>
#include <cuda_bf16.h>
#include <math.h>

#define CS   1024
#define NH   16
#define HD   64
#define SEQ  1024
#define FINF 1e30f

// ---------------- scratch (device globals) ----------------
__device__ float g_g[SEQ * CS];
__device__ float g_z[(size_t)NH * SEQ * SEQ];
__constant__ float cWz[128 * 16];

// bf16 hi/lo split buffers
__device__ __align__(16) __nv_bfloat16 b_s_h[SEQ*CS],  b_s_l[SEQ*CS];
__device__ __align__(16) __nv_bfloat16 b_k_h[SEQ*CS],  b_k_l[SEQ*CS];
__device__ __align__(16) __nv_bfloat16 b_Wq_h[CS*CS],  b_Wq_l[CS*CS];
__device__ __align__(16) __nv_bfloat16 b_Wk_h[CS*CS],  b_Wk_l[CS*CS];
__device__ __align__(16) __nv_bfloat16 b_Wv_h[CS*CS],  b_Wv_l[CS*CS];
__device__ __align__(16) __nv_bfloat16 b_Wg_h[CS*CS],  b_Wg_l[CS*CS];
__device__ __align__(16) __nv_bfloat16 b_Wo_h[CS*CS],  b_Wo_l[CS*CS];
__device__ __align__(16) __nv_bfloat16 b_a_h[SEQ*CS],  b_a_l[SEQ*CS];
// projected q/k/v as bf16 hi/lo, layout [row][h*64+d]
__device__ __align__(16) __nv_bfloat16 f_q_h[SEQ*CS],  f_q_l[SEQ*CS];
__device__ __align__(16) __nv_bfloat16 f_k_h[SEQ*CS],  f_k_l[SEQ*CS];
__device__ __align__(16) __nv_bfloat16 f_v_h[SEQ*CS],  f_v_l[SEQ*CS];

// ---------------- primitives ----------------
__device__ __forceinline__ void mma_bf16(float d[4], const unsigned a[4], const unsigned b[2]) {
    asm volatile(
        "mma.sync.aligned.m16n8k16.row.col.f32.bf16.bf16.f32 "
        "{%0,%1,%2,%3},{%4,%5,%6,%7},{%8,%9},{%0,%1,%2,%3};\n"
        : "+f"(d[0]), "+f"(d[1]), "+f"(d[2]), "+f"(d[3])
        : "r"(a[0]), "r"(a[1]), "r"(a[2]), "r"(a[3]), "r"(b[0]), "r"(b[1]));
}
__device__ __forceinline__ void ldsm4(unsigned r[4], unsigned addr) {
    asm volatile("ldmatrix.sync.aligned.m8n8.x4.shared.b16 {%0,%1,%2,%3}, [%4];\n"
                 : "=r"(r[0]), "=r"(r[1]), "=r"(r[2]), "=r"(r[3]) : "r"(addr));
}
__device__ __forceinline__ void ldsm2(unsigned r[2], unsigned addr) {
    asm volatile("ldmatrix.sync.aligned.m8n8.x2.shared.b16 {%0,%1}, [%2];\n"
                 : "=r"(r[0]), "=r"(r[1]) : "r"(addr));
}
__device__ __forceinline__ void ldsm2t(unsigned r[2], unsigned addr) {
    asm volatile("ldmatrix.sync.aligned.m8n8.x2.trans.shared.b16 {%0,%1}, [%2];\n"
                 : "=r"(r[0]), "=r"(r[1]) : "r"(addr));
}
__device__ __forceinline__ unsigned smem_u32(const void* p) {
    return (unsigned)__cvta_generic_to_shared(p);
}
__device__ __forceinline__ void cp16(unsigned dst, const void* src) {
    asm volatile("cp.async.cg.shared.global [%0], [%1], 16;\n" :: "r"(dst), "l"(src));
}
__device__ __forceinline__ unsigned packbf(float a, float b) {
    __nv_bfloat162 t = __floats2bfloat162_rn(a, b);
    return *(unsigned*)&t;
}
__device__ __forceinline__ void split1(float x, __nv_bfloat16& h, __nv_bfloat16& l) {
    h = __float2bfloat16_rn(x);
    l = __float2bfloat16_rn(x - __bfloat162float(h));
}
__device__ __forceinline__ void split4_store(float4 v, __nv_bfloat16* ph, __nv_bfloat16* pl) {
    __nv_bfloat16 h0,h1,h2,h3,l0,l1,l2,l3;
    split1(v.x,h0,l0); split1(v.y,h1,l1); split1(v.z,h2,l2); split1(v.w,h3,l3);
    __nv_bfloat162 hh0 = __halves2bfloat162(h0,h1), hh1 = __halves2bfloat162(h2,h3);
    __nv_bfloat162 ll0 = __halves2bfloat162(l0,l1), ll1 = __halves2bfloat162(l2,l3);
    uint2 hu; hu.x = *(unsigned*)&hh0; hu.y = *(unsigned*)&hh1;
    uint2 lu; lu.x = *(unsigned*)&ll0; lu.y = *(unsigned*)&ll1;
    *(uint2*)ph = hu; *(uint2*)pl = lu;
}
// split a float pair, store two bf162 words
__device__ __forceinline__ void split2_store(float a, float b,
                                             __nv_bfloat16* ph, __nv_bfloat16* pl) {
    __nv_bfloat16 h0,h1,l0,l1;
    split1(a,h0,l0); split1(b,h1,l1);
    __nv_bfloat162 hh = __halves2bfloat162(h0,h1);
    __nv_bfloat162 ll = __halves2bfloat162(l0,l1);
    *(unsigned*)ph = *(unsigned*)&hh;
    *(unsigned*)pl = *(unsigned*)&ll;
}

// Kernel S: split the 7 fp32 source matrices into bf16 hi/lo
__global__ __launch_bounds__(256)
void split_kernel(const float* __restrict__ s,  const float* __restrict__ kin,
                  const float* __restrict__ Wq, const float* __restrict__ Wk,
                  const float* __restrict__ Wv, const float* __restrict__ Wg,
                  const float* __restrict__ Wo)
{
    const float* src; __nv_bfloat16 *dh, *dl;
    switch (blockIdx.y) {
        case 0:  src = s;   dh = b_s_h;  dl = b_s_l;  break;
        case 1:  src = kin; dh = b_k_h;  dl = b_k_l;  break;
        case 2:  src = Wq;  dh = b_Wq_h; dl = b_Wq_l; break;
        case 3:  src = Wk;  dh = b_Wk_h; dl = b_Wk_l; break;
        case 4:  src = Wv;  dh = b_Wv_h; dl = b_Wv_l; break;
        case 5:  src = Wg;  dh = b_Wg_h; dl = b_Wg_l; break;
        default: src = Wo;  dh = b_Wo_h; dl = b_Wo_l; break;
    }
    int i = (blockIdx.x * 256 + threadIdx.x) * 4;
    float4 v = *(const float4*)(src + i);
    split4_store(v, dh + i, dl + i);
}

// ---------------- bf16x3 tensor-core GEMM core (128x128, K=1024) ----------------
#define LDT 40

__device__ __forceinline__ void mma_core(
    const __nv_bfloat16* __restrict__ Ah, const __nv_bfloat16* __restrict__ Al,
    const __nv_bfloat16* __restrict__ Bh, const __nv_bfloat16* __restrict__ Bl,
    int m0, int n0, float acc[4][4][4])
{
    __shared__ __nv_bfloat16 sAh[128*LDT], sAl[128*LDT], sBh[128*LDT], sBl[128*LDT];

    const int tid  = threadIdx.x;
    const int lane = tid & 31;
    const int warp = tid >> 5;
    const int wm   = warp >> 2;
    const int wn   = warp & 3;

    #pragma unroll
    for (int mt = 0; mt < 4; mt++)
        #pragma unroll
        for (int nt = 0; nt < 4; nt++)
            #pragma unroll
            for (int u = 0; u < 4; u++) acc[mt][nt][u] = 0.f;

    int r0 = tid >> 2,          s0 = (tid & 3) * 8;
    int r1 = (tid + 256) >> 2,  s1 = (tid & 3) * 8;

    uint4 pAh0, pAh1, pAl0, pAl1, pBh0, pBh1, pBl0, pBl1;
    {
        size_t a0 = (size_t)(m0 + r0) * CS + s0, a1 = (size_t)(m0 + r1) * CS + s1;
        size_t b0 = (size_t)(n0 + r0) * CS + s0, b1 = (size_t)(n0 + r1) * CS + s1;
        pAh0 = *(const uint4*)(Ah + a0); pAh1 = *(const uint4*)(Ah + a1);
        pAl0 = *(const uint4*)(Al + a0); pAl1 = *(const uint4*)(Al + a1);
        pBh0 = *(const uint4*)(Bh + b0); pBh1 = *(const uint4*)(Bh + b1);
        pBl0 = *(const uint4*)(Bl + b0); pBl1 = *(const uint4*)(Bl + b1);
    }

    const int amat = lane >> 3, arow = lane & 7;
    const int a_r  = wm * 64 + (amat & 1) * 8 + arow;
    const int a_c  = (amat >> 1) * 8;
    const int b_r  = wn * 32 + arow;
    const int b_c  = ((lane >> 3) & 1) * 8;

    const unsigned uAh = smem_u32(sAh), uAl = smem_u32(sAl);
    const unsigned uBh = smem_u32(sBh), uBl = smem_u32(sBl);

    for (int k0 = 0; k0 < CS; k0 += 32) {
        *(uint4*)&sAh[r0*LDT + s0] = pAh0; *(uint4*)&sAh[r1*LDT + s1] = pAh1;
        *(uint4*)&sAl[r0*LDT + s0] = pAl0; *(uint4*)&sAl[r1*LDT + s1] = pAl1;
        *(uint4*)&sBh[r0*LDT + s0] = pBh0; *(uint4*)&sBh[r1*LDT + s1] = pBh1;
        *(uint4*)&sBl[r0*LDT + s0] = pBl0; *(uint4*)&sBl[r1*LDT + s1] = pBl1;
        __syncthreads();

        if (k0 + 32 < CS) {
            int kn = k0 + 32;
            size_t a0 = (size_t)(m0 + r0) * CS + kn + s0, a1 = (size_t)(m0 + r1) * CS + kn + s1;
            size_t b0 = (size_t)(n0 + r0) * CS + kn + s0, b1 = (size_t)(n0 + r1) * CS + kn + s1;
            pAh0 = *(const uint4*)(Ah + a0); pAh1 = *(const uint4*)(Ah + a1);
            pAl0 = *(const uint4*)(Al + a0); pAl1 = *(const uint4*)(Al + a1);
            pBh0 = *(const uint4*)(Bh + b0); pBh1 = *(const uint4*)(Bh + b1);
            pBl0 = *(const uint4*)(Bl + b0); pBl1 = *(const uint4*)(Bl + b1);
        }

        #pragma unroll
        for (int ks = 0; ks < 32; ks += 16) {
            unsigned afh[4][4], afl[4][4], bfh[4][2], bfl[4][2];
            #pragma unroll
            for (int mt = 0; mt < 4; mt++) {
                unsigned off = ((a_r + mt*16) * LDT + ks + a_c) * 2;
                ldsm4(afh[mt], uAh + off);
                ldsm4(afl[mt], uAl + off);
            }
            #pragma unroll
            for (int nt = 0; nt < 4; nt++) {
                unsigned off = ((b_r + nt*8) * LDT + ks + b_c) * 2;
                ldsm2(bfh[nt], uBh + off);
                ldsm2(bfl[nt], uBl + off);
            }
            #pragma unroll
            for (int mt = 0; mt < 4; mt++)
                #pragma unroll
                for (int nt = 0; nt < 4; nt++) {
                    mma_bf16(acc[mt][nt], afh[mt], bfh[nt]);
                    mma_bf16(acc[mt][nt], afh[mt], bfl[nt]);
                    mma_bf16(acc[mt][nt], afl[mt], bfh[nt]);
                }
        }
        __syncthreads();
    }
}

// Kernel 1: projections.  z: 0=q(+bq)->f_q, 1=k->f_k, 2=v->f_v, 3=g(sigmoid)->g_g fp32
__global__ __launch_bounds__(256)
void proj_mma(const float* __restrict__ bq)
{
    const __nv_bfloat16 *Ah, *Al, *Bh, *Bl;
    __nv_bfloat16 *OH = nullptr, *OL = nullptr;
    const float* bias = nullptr;
    switch (blockIdx.z) {
        case 0:  Ah=b_s_h; Al=b_s_l; Bh=b_Wq_h; Bl=b_Wq_l; OH=f_q_h; OL=f_q_l; bias=bq; break;
        case 1:  Ah=b_k_h; Al=b_k_l; Bh=b_Wk_h; Bl=b_Wk_l; OH=f_k_h; OL=f_k_l; break;
        case 2:  Ah=b_k_h; Al=b_k_l; Bh=b_Wv_h; Bl=b_Wv_l; OH=f_v_h; OL=f_v_l; break;
        default: Ah=b_s_h; Al=b_s_l; Bh=b_Wg_h; Bl=b_Wg_l; break;
    }
    const int m0 = blockIdx.y * 128, n0 = blockIdx.x * 128;
    float acc[4][4][4];
    mma_core(Ah, Al, Bh, Bl, m0, n0, acc);

    const int lane = threadIdx.x & 31, warp = threadIdx.x >> 5;
    const int wm = warp >> 2, wn = warp & 3;
    const int lr = lane >> 2, lc = (lane & 3) * 2;
    #pragma unroll
    for (int mt = 0; mt < 4; mt++)
        #pragma unroll
        for (int nt = 0; nt < 4; nt++) {
            int row = m0 + wm*64 + mt*16 + lr;
            int col = n0 + wn*32 + nt*8 + lc;
            float v0 = acc[mt][nt][0], v1 = acc[mt][nt][1];
            float v2 = acc[mt][nt][2], v3 = acc[mt][nt][3];
            if (bias) { float b0_ = bias[col], b1_ = bias[col+1];
                        v0 += b0_; v1 += b1_; v2 += b0_; v3 += b1_; }
            if (blockIdx.z == 3) {
                v0 = 1.0f/(1.0f+__expf(-v0)); v1 = 1.0f/(1.0f+__expf(-v1));
                v2 = 1.0f/(1.0f+__expf(-v2)); v3 = 1.0f/(1.0f+__expf(-v3));
                *(float2*)&g_g[(size_t)row*CS + col]     = make_float2(v0, v1);
                *(float2*)&g_g[(size_t)(row+8)*CS + col] = make_float2(v2, v3);
            } else {
                split2_store(v0, v1, OH + (size_t)row*CS + col,     OL + (size_t)row*CS + col);
                split2_store(v2, v3, OH + (size_t)(row+8)*CS + col, OL + (size_t)(row+8)*CS + col);
            }
        }
}

// Kernel 6: out = (g*o) @ Wo^T
__global__ __launch_bounds__(256)
void out_mma(float* __restrict__ out)
{
    const int m0 = blockIdx.y * 128, n0 = blockIdx.x * 128;
    float acc[4][4][4];
    mma_core(b_a_h, b_a_l, b_Wo_h, b_Wo_l, m0, n0, acc);

    const int lane = threadIdx.x & 31, warp = threadIdx.x >> 5;
    const int wm = warp >> 2, wn = warp & 3;
    const int lr = lane >> 2, lc = (lane & 3) * 2;
    #pragma unroll
    for (int mt = 0; mt < 4; mt++)
        #pragma unroll
        for (int nt = 0; nt < 4; nt++) {
            int row = m0 + wm*64 + mt*16 + lr;
            int col = n0 + wn*32 + nt*8 + lc;
            *(float2*)&out[(size_t)row*CS + col]     = make_float2(acc[mt][nt][0], acc[mt][nt][1]);
            *(float2*)&out[(size_t)(row+8)*CS + col] = make_float2(acc[mt][nt][2], acc[mt][nt][3]);
        }
}

// ---------------- zbias: z[h,i,j] = bias[i,j,:]·Wz[:,h] + mask ----------------
__global__ __launch_bounds__(256)
void zbias_kernel(const float* __restrict__ bias, const float* __restrict__ mask)
{
    __shared__ float sb[256][33];
    const int tid = threadIdx.x;
    const long p0 = (long)blockIdx.x * 256;

    float acc[16];
    #pragma unroll
    for (int h = 0; h < 16; h++) acc[h] = 0.f;

    for (int cb = 0; cb < 4; cb++) {
        __syncthreads();
        #pragma unroll
        for (int r = 0; r < 8; r++) {
            int f = tid + r * 256;
            int pair = f >> 3, cq = f & 7;
            float4 v = *(const float4*)&bias[(p0 + pair) * 128 + cb * 32 + cq * 4];
            sb[pair][cq*4+0] = v.x; sb[pair][cq*4+1] = v.y;
            sb[pair][cq*4+2] = v.z; sb[pair][cq*4+3] = v.w;
        }
        __syncthreads();
        #pragma unroll
        for (int c = 0; c < 32; c++) {
            float bvf = sb[tid][c];
            int cg = cb * 32 + c;
            #pragma unroll
            for (int h = 0; h < 16; h++)
                acc[h] += bvf * cWz[cg * 16 + h];
        }
    }
    const long p = p0 + tid;
    const int j = (int)(p & (SEQ - 1));
    const float madd = (1.0f - mask[j]) * (-1000000.0f);
    #pragma unroll
    for (int h = 0; h < 16; h++)
        g_z[((long)h << 20) + p] = acc[h] + madd;
}

// ---------------- flash attention: S=qk/8+z, online softmax, P·V, gate ----------------
// grid (8 i-blocks, 16 heads), 256 threads. All mma in bf16x3.
#define LQ 72   // smem row stride (64 + 8 pad)
#define FLASH_SMEM (6 * 128 * LQ * 2)

__global__ __launch_bounds__(256)
void flash_kernel()
{
    extern __shared__ __nv_bfloat16 fsm[];
    __nv_bfloat16* sqh = fsm;
    __nv_bfloat16* sql = sqh + 128*LQ;
    __nv_bfloat16* skh = sql + 128*LQ;
    __nv_bfloat16* skl = skh + 128*LQ;
    __nv_bfloat16* svh = skl + 128*LQ;
    __nv_bfloat16* svl = svh + 128*LQ;

    const int h  = blockIdx.y;
    const int i0 = blockIdx.x * 128;
    const int tid  = threadIdx.x;
    const int lane = tid & 31;
    const int warp = tid >> 5;
    const int lr = lane >> 2, t4 = lane & 3;

    // load q tile (128 x 64 hi/lo)
    #pragma unroll
    for (int i = 0; i < 4; i++) {
        int u = tid + i*256;
        int r = u >> 3, cc = (u & 7) * 8;
        *(uint4*)&sqh[r*LQ + cc] = *(const uint4*)&f_q_h[(size_t)(i0+r)*CS + h*HD + cc];
        *(uint4*)&sql[r*LQ + cc] = *(const uint4*)&f_q_l[(size_t)(i0+r)*CS + h*HD + cc];
    }

    const unsigned uqh = smem_u32(sqh), uql = smem_u32(sql);
    const unsigned ukh = smem_u32(skh), ukl = smem_u32(skl);
    const unsigned uvh = smem_u32(svh), uvl = smem_u32(svl);

    // A-frag (q) addressing
    const unsigned qoff = ((warp*16 + (lane & 15)) * LQ + ((lane >> 4) * 8)) * 2;
    // B-frag (k) addressing
    const unsigned koff = (((lane & 7)) * LQ + ((lane >> 3) & 1) * 8) * 2;
    // B-frag (v, trans): row j, col d
    const unsigned voff = (((lane & 7) + ((lane >> 3) & 1) * 8) * LQ) * 2;

    float m_prev0 = -FINF, m_prev1 = -FINF;
    float l0 = 0.f, l1 = 0.f;
    float oac[8][4];
    #pragma unroll
    for (int d = 0; d < 8; d++)
        #pragma unroll
        for (int u = 0; u < 4; u++) oac[d][u] = 0.f;

    const int zrow = i0 + warp*16 + lr;
    const float* Zbase = g_z + ((long)h << 20) + (long)zrow * SEQ + t4*2;

    for (int jt = 0; jt < 8; jt++) {
        const int j0 = jt * 128;
        __syncthreads();
        // async-load k/v tiles (hi+lo), 16B each
        #pragma unroll
        for (int i = 0; i < 4; i++) {
            int u = tid + i*256;
            int r = u >> 3, cc = (u & 7) * 8;
            unsigned so = (r*LQ + cc) * 2;
            size_t go = (size_t)(j0 + r) * CS + h*HD + cc;
            cp16(ukh + so, f_k_h + go);
            cp16(ukl + so, f_k_l + go);
            cp16(uvh + so, f_v_h + go);
            cp16(uvl + so, f_v_l + go);
        }
        asm volatile("cp.async.commit_group;\ncp.async.wait_group 0;\n" ::: "memory");
        __syncthreads();

        // ---- S = q·k^T (bf16x3) ----
        float sa[16][4];
        #pragma unroll
        for (int nt = 0; nt < 16; nt++)
            #pragma unroll
            for (int u = 0; u < 4; u++) sa[nt][u] = 0.f;

        #pragma unroll
        for (int ks = 0; ks < 64; ks += 16) {
            unsigned ah[4], al[4];
            ldsm4(ah, uqh + qoff + ks*2);
            ldsm4(al, uql + qoff + ks*2);
            #pragma unroll
            for (int nt = 0; nt < 16; nt++) {
                unsigned bh[2], bl[2];
                unsigned off = koff + (nt*8*LQ + ks) * 2;
                ldsm2(bh, ukh + off);
                ldsm2(bl, ukl + off);
                mma_bf16(sa[nt], ah, bh);
                mma_bf16(sa[nt], ah, bl);
                mma_bf16(sa[nt], al, bh);
            }
        }

        // ---- scale + z, tile row-max ----
        float mx0 = -FINF, mx1 = -FINF;
        #pragma unroll
        for (int nt = 0; nt < 16; nt++) {
            float2 z0 = *(const float2*)(Zbase + j0 + nt*8);
            float2 z1 = *(const float2*)(Zbase + 8*SEQ + j0 + nt*8);
            sa[nt][0] = sa[nt][0]*0.125f + z0.x;
            sa[nt][1] = sa[nt][1]*0.125f + z0.y;
            sa[nt][2] = sa[nt][2]*0.125f + z1.x;
            sa[nt][3] = sa[nt][3]*0.125f + z1.y;
            mx0 = fmaxf(mx0, fmaxf(sa[nt][0], sa[nt][1]));
            mx1 = fmaxf(mx1, fmaxf(sa[nt][2], sa[nt][3]));
        }
        mx0 = fmaxf(mx0, __shfl_xor_sync(0xffffffffu, mx0, 1));
        mx0 = fmaxf(mx0, __shfl_xor_sync(0xffffffffu, mx0, 2));
        mx1 = fmaxf(mx1, __shfl_xor_sync(0xffffffffu, mx1, 1));
        mx1 = fmaxf(mx1, __shfl_xor_sync(0xffffffffu, mx1, 2));

        float mn0 = fmaxf(m_prev0, mx0), mn1 = fmaxf(m_prev1, mx1);
        float fa0 = __expf(m_prev0 - mn0), fa1 = __expf(m_prev1 - mn1);
        m_prev0 = mn0; m_prev1 = mn1;

        float sum0 = 0.f, sum1 = 0.f;
        #pragma unroll
        for (int nt = 0; nt < 16; nt++) {
            sa[nt][0] = __expf(sa[nt][0] - mn0);
            sa[nt][1] = __expf(sa[nt][1] - mn0);
            sa[nt][2] = __expf(sa[nt][2] - mn1);
            sa[nt][3] = __expf(sa[nt][3] - mn1);
            sum0 += sa[nt][0] + sa[nt][1];
            sum1 += sa[nt][2] + sa[nt][3];
        }
        sum0 += __shfl_xor_sync(0xffffffffu, sum0, 1);
        sum0 += __shfl_xor_sync(0xffffffffu, sum0, 2);
        sum1 += __shfl_xor_sync(0xffffffffu, sum1, 1);
        sum1 += __shfl_xor_sync(0xffffffffu, sum1, 2);
        l0 = l0 * fa0 + sum0;
        l1 = l1 * fa1 + sum1;

        #pragma unroll
        for (int d = 0; d < 8; d++) {
            oac[d][0] *= fa0; oac[d][1] *= fa0;
            oac[d][2] *= fa1; oac[d][3] *= fa1;
        }

        // ---- O += P·V (bf16x3; P hi/lo from register fragments) ----
        #pragma unroll
        for (int kt = 0; kt < 8; kt++) {
            float p00 = sa[2*kt][0],   p01 = sa[2*kt][1];
            float p02 = sa[2*kt][2],   p03 = sa[2*kt][3];
            float p10 = sa[2*kt+1][0], p11 = sa[2*kt+1][1];
            float p12 = sa[2*kt+1][2], p13 = sa[2*kt+1][3];

            unsigned pah[4], pal[4];
            pah[0] = packbf(p00, p01); pah[1] = packbf(p02, p03);
            pah[2] = packbf(p10, p11); pah[3] = packbf(p12, p13);
            {
                __nv_bfloat162 t0 = *(__nv_bfloat162*)&pah[0];
                __nv_bfloat162 t1 = *(__nv_bfloat162*)&pah[1];
                __nv_bfloat162 t2 = *(__nv_bfloat162*)&pah[2];
                __nv_bfloat162 t3 = *(__nv_bfloat162*)&pah[3];
                pal[0] = packbf(p00 - __bfloat162float(t0.x), p01 - __bfloat162float(t0.y));
                pal[1] = packbf(p02 - __bfloat162float(t1.x), p03 - __bfloat162float(t1.y));
                pal[2] = packbf(p10 - __bfloat162float(t2.x), p11 - __bfloat162float(t2.y));
                pal[3] = packbf(p12 - __bfloat162float(t3.x), p13 - __bfloat162float(t3.y));
            }

            #pragma unroll
            for (int dnt = 0; dnt < 8; dnt++) {
                unsigned bh[2], bl[2];
                unsigned off = voff + (kt*16*LQ + dnt*8) * 2;
                ldsm2t(bh, uvh + off);
                ldsm2t(bl, uvl + off);
                mma_bf16(oac[dnt], pah, bh);
                mma_bf16(oac[dnt], pah, bl);
                mma_bf16(oac[dnt], pal, bh);
            }
        }
    }

    // ---- epilogue: o/l, gate, split to bf16 hi/lo for out_mma ----
    float il0 = 1.0f / l0, il1 = 1.0f / l1;
    const int row0 = i0 + warp*16 + lr;
    #pragma unroll
    for (int dnt = 0; dnt < 8; dnt++) {
        int col = h*HD + dnt*8 + t4*2;
        float2 gv0 = *(const float2*)&g_g[(size_t)row0*CS + col];
        float2 gv1 = *(const float2*)&g_g[(size_t)(row0+8)*CS + col];
        float a0 = oac[dnt][0]*il0*gv0.x, a1 = oac[dnt][1]*il0*gv0.y;
        float a2 = oac[dnt][2]*il1*gv1.x, a3 = oac[dnt][3]*il1*gv1.y;
        split2_store(a0, a1, b_a_h + (size_t)row0*CS + col,     b_a_l + (size_t)row0*CS + col);
        split2_store(a2, a3, b_a_h + (size_t)(row0+8)*CS + col, b_a_l + (size_t)(row0+8)*CS + col);
    }
}

// =====================================================================
extern "C" void kernel_launch(void* const* d_in, const int* in_sizes, int n_in,
                              void* d_out, int out_size)
{
    const float* s    = (const float*)d_in[0];
    const float* kin  = (const float*)d_in[1];
    const float* mask = (const float*)d_in[2];
    const float* bias = (const float*)d_in[3];
    const float* Wq   = (const float*)d_in[4];
    const float* bq   = (const float*)d_in[5];
    const float* Wk   = (const float*)d_in[6];
    const float* Wv   = (const float*)d_in[7];
    const float* Wg   = (const float*)d_in[8];
    const float* Wo   = (const float*)d_in[9];
    const float* Wz   = (const float*)d_in[10];
    float* out = (float*)d_out;

    cudaFuncSetAttribute(flash_kernel,
                         cudaFuncAttributeMaxDynamicSharedMemorySize, FLASH_SMEM);
    cudaMemcpyToSymbolAsync(cWz, Wz, 128 * 16 * sizeof(float), 0,
                            cudaMemcpyDeviceToDevice);

    split_kernel<<<dim3(1024, 7), 256>>>(s, kin, Wq, Wk, Wv, Wg, Wo);
    proj_mma    <<<dim3(8, 8, 4),  256>>>(bq);
    zbias_kernel<<<4096,           256>>>(bias, mask);
    flash_kernel<<<dim3(8, 16),    256, FLASH_SMEM>>>();
    out_mma     <<<dim3(8, 8),     256>>>(out);
}

// round 4
// speedup vs baseline: 1.8964x; 1.0033x over previous
#include <cuda_runtime.h>
#include <cuda_bf16.h>
#include <math.h>

#define CS   1024
#define NH   16
#define HD   64
#define SEQ  1024
#define FINF 1e30f

// ---------------- scratch (device globals) ----------------
__device__ float g_g[SEQ * CS];
__device__ float g_z[(size_t)NH * SEQ * SEQ];
__constant__ float cWz[128 * 16];

__device__ __align__(16) __nv_bfloat16 b_s_h[SEQ*CS],  b_s_l[SEQ*CS];
__device__ __align__(16) __nv_bfloat16 b_k_h[SEQ*CS],  b_k_l[SEQ*CS];
__device__ __align__(16) __nv_bfloat16 b_Wq_h[CS*CS],  b_Wq_l[CS*CS];
__device__ __align__(16) __nv_bfloat16 b_Wk_h[CS*CS],  b_Wk_l[CS*CS];
__device__ __align__(16) __nv_bfloat16 b_Wv_h[CS*CS],  b_Wv_l[CS*CS];
__device__ __align__(16) __nv_bfloat16 b_Wg_h[CS*CS],  b_Wg_l[CS*CS];
__device__ __align__(16) __nv_bfloat16 b_Wo_h[CS*CS],  b_Wo_l[CS*CS];
__device__ __align__(16) __nv_bfloat16 b_a_h[SEQ*CS],  b_a_l[SEQ*CS];
__device__ __align__(16) __nv_bfloat16 f_q_h[SEQ*CS],  f_q_l[SEQ*CS];
__device__ __align__(16) __nv_bfloat16 f_k_h[SEQ*CS],  f_k_l[SEQ*CS];
__device__ __align__(16) __nv_bfloat16 f_v_h[SEQ*CS],  f_v_l[SEQ*CS];

// ---------------- primitives ----------------
__device__ __forceinline__ void mma_bf16(float d[4], const unsigned a[4], const unsigned b[2]) {
    asm volatile(
        "mma.sync.aligned.m16n8k16.row.col.f32.bf16.bf16.f32 "
        "{%0,%1,%2,%3},{%4,%5,%6,%7},{%8,%9},{%0,%1,%2,%3};\n"
        : "+f"(d[0]), "+f"(d[1]), "+f"(d[2]), "+f"(d[3])
        : "r"(a[0]), "r"(a[1]), "r"(a[2]), "r"(a[3]), "r"(b[0]), "r"(b[1]));
}
__device__ __forceinline__ void ldsm4(unsigned r[4], unsigned addr) {
    asm volatile("ldmatrix.sync.aligned.m8n8.x4.shared.b16 {%0,%1,%2,%3}, [%4];\n"
                 : "=r"(r[0]), "=r"(r[1]), "=r"(r[2]), "=r"(r[3]) : "r"(addr));
}
__device__ __forceinline__ void ldsm2(unsigned r[2], unsigned addr) {
    asm volatile("ldmatrix.sync.aligned.m8n8.x2.shared.b16 {%0,%1}, [%2];\n"
                 : "=r"(r[0]), "=r"(r[1]) : "r"(addr));
}
__device__ __forceinline__ void ldsm2t(unsigned r[2], unsigned addr) {
    asm volatile("ldmatrix.sync.aligned.m8n8.x2.trans.shared.b16 {%0,%1}, [%2];\n"
                 : "=r"(r[0]), "=r"(r[1]) : "r"(addr));
}
__device__ __forceinline__ unsigned smem_u32(const void* p) {
    return (unsigned)__cvta_generic_to_shared(p);
}
__device__ __forceinline__ void cp16(unsigned dst, const void* src) {
    asm volatile("cp.async.cg.shared.global [%0], [%1], 16;\n" :: "r"(dst), "l"(src));
}
__device__ __forceinline__ void cp_commit() {
    asm volatile("cp.async.commit_group;\n" ::: "memory");
}
__device__ __forceinline__ void cp_wait1() {
    asm volatile("cp.async.wait_group 1;\n" ::: "memory");
}
__device__ __forceinline__ void cp_wait0() {
    asm volatile("cp.async.wait_group 0;\n" ::: "memory");
}
__device__ __forceinline__ unsigned packbf(float a, float b) {
    __nv_bfloat162 t = __floats2bfloat162_rn(a, b);
    return *(unsigned*)&t;
}
__device__ __forceinline__ void split1(float x, __nv_bfloat16& h, __nv_bfloat16& l) {
    h = __float2bfloat16_rn(x);
    l = __float2bfloat16_rn(x - __bfloat162float(h));
}
__device__ __forceinline__ void split4_store(float4 v, __nv_bfloat16* ph, __nv_bfloat16* pl) {
    __nv_bfloat16 h0,h1,h2,h3,l0,l1,l2,l3;
    split1(v.x,h0,l0); split1(v.y,h1,l1); split1(v.z,h2,l2); split1(v.w,h3,l3);
    __nv_bfloat162 hh0 = __halves2bfloat162(h0,h1), hh1 = __halves2bfloat162(h2,h3);
    __nv_bfloat162 ll0 = __halves2bfloat162(l0,l1), ll1 = __halves2bfloat162(l2,l3);
    uint2 hu; hu.x = *(unsigned*)&hh0; hu.y = *(unsigned*)&hh1;
    uint2 lu; lu.x = *(unsigned*)&ll0; lu.y = *(unsigned*)&ll1;
    *(uint2*)ph = hu; *(uint2*)pl = lu;
}
__device__ __forceinline__ void split2_store(float a, float b,
                                             __nv_bfloat16* ph, __nv_bfloat16* pl) {
    __nv_bfloat16 h0,h1,l0,l1;
    split1(a,h0,l0); split1(b,h1,l1);
    __nv_bfloat162 hh = __halves2bfloat162(h0,h1);
    __nv_bfloat162 ll = __halves2bfloat162(l0,l1);
    *(unsigned*)ph = *(unsigned*)&hh;
    *(unsigned*)pl = *(unsigned*)&ll;
}

// Kernel S: split the 7 fp32 source matrices into bf16 hi/lo
__global__ __launch_bounds__(256)
void split_kernel(const float* __restrict__ s,  const float* __restrict__ kin,
                  const float* __restrict__ Wq, const float* __restrict__ Wk,
                  const float* __restrict__ Wv, const float* __restrict__ Wg,
                  const float* __restrict__ Wo)
{
    const float* src; __nv_bfloat16 *dh, *dl;
    switch (blockIdx.y) {
        case 0:  src = s;   dh = b_s_h;  dl = b_s_l;  break;
        case 1:  src = kin; dh = b_k_h;  dl = b_k_l;  break;
        case 2:  src = Wq;  dh = b_Wq_h; dl = b_Wq_l; break;
        case 3:  src = Wk;  dh = b_Wk_h; dl = b_Wk_l; break;
        case 4:  src = Wv;  dh = b_Wv_h; dl = b_Wv_l; break;
        case 5:  src = Wg;  dh = b_Wg_h; dl = b_Wg_l; break;
        default: src = Wo;  dh = b_Wo_h; dl = b_Wo_l; break;
    }
    int i = (blockIdx.x * 256 + threadIdx.x) * 4;
    float4 v = *(const float4*)(src + i);
    split4_store(v, dh + i, dl + i);
}

// ---------------- bf16x3 GEMM core, 2-stage cp.async pipeline ----------------
#define LDT 40
#define GST (4*128*LDT)                 // halves per stage
#define GSMEM (2 * GST * 2)             // bytes (2 stages)

__device__ __forceinline__ void mma_core(
    const __nv_bfloat16* __restrict__ Ah, const __nv_bfloat16* __restrict__ Al,
    const __nv_bfloat16* __restrict__ Bh, const __nv_bfloat16* __restrict__ Bl,
    int m0, int n0, float acc[4][4][4])
{
    extern __shared__ __nv_bfloat16 gsm[];

    const int tid  = threadIdx.x;
    const int lane = tid & 31;
    const int warp = tid >> 5;
    const int wm   = warp >> 2;
    const int wn   = warp & 3;

    #pragma unroll
    for (int mt = 0; mt < 4; mt++)
        #pragma unroll
        for (int nt = 0; nt < 4; nt++)
            #pragma unroll
            for (int u = 0; u < 4; u++) acc[mt][nt][u] = 0.f;

    const int r0 = tid >> 2,         c0 = (tid & 3) * 8;
    const int r1 = (tid + 256) >> 2;

    const unsigned ub = smem_u32(gsm);
    const unsigned oAl = 128*LDT*2, oBh = 2*128*LDT*2, oBl = 3*128*LDT*2;

    const int amat = lane >> 3, arow = lane & 7;
    const int a_r  = wm * 64 + (amat & 1) * 8 + arow;
    const int a_c  = (amat >> 1) * 8;
    const int b_r  = wn * 32 + arow;
    const int b_c  = ((lane >> 3) & 1) * 8;

    // prologue: stage 0
    {
        size_t a0 = (size_t)(m0 + r0) * CS + c0, a1 = (size_t)(m0 + r1) * CS + c0;
        size_t b0 = (size_t)(n0 + r0) * CS + c0, b1 = (size_t)(n0 + r1) * CS + c0;
        unsigned s0o = (unsigned)(r0*LDT + c0) * 2, s1o = (unsigned)(r1*LDT + c0) * 2;
        cp16(ub + s0o,       Ah + a0); cp16(ub + s1o,       Ah + a1);
        cp16(ub + oAl + s0o, Al + a0); cp16(ub + oAl + s1o, Al + a1);
        cp16(ub + oBh + s0o, Bh + b0); cp16(ub + oBh + s1o, Bh + b1);
        cp16(ub + oBl + s0o, Bl + b0); cp16(ub + oBl + s1o, Bl + b1);
        cp_commit();
    }

    for (int it = 0; it < 32; it++) {
        const int k0 = it * 32;
        const bool more = (k0 + 32 < CS);
        if (more) {
            const int kn = k0 + 32;
            const unsigned sb = ub + ((it + 1) & 1) * (GST * 2);
            size_t a0 = (size_t)(m0 + r0) * CS + kn + c0, a1 = (size_t)(m0 + r1) * CS + kn + c0;
            size_t b0 = (size_t)(n0 + r0) * CS + kn + c0, b1 = (size_t)(n0 + r1) * CS + kn + c0;
            unsigned s0o = (unsigned)(r0*LDT + c0) * 2, s1o = (unsigned)(r1*LDT + c0) * 2;
            cp16(sb + s0o,       Ah + a0); cp16(sb + s1o,       Ah + a1);
            cp16(sb + oAl + s0o, Al + a0); cp16(sb + oAl + s1o, Al + a1);
            cp16(sb + oBh + s0o, Bh + b0); cp16(sb + oBh + s1o, Bh + b1);
            cp16(sb + oBl + s0o, Bl + b0); cp16(sb + oBl + s1o, Bl + b1);
            cp_commit();
            cp_wait1();
        } else {
            cp_wait0();
        }
        __syncthreads();

        const unsigned sb = ub + (it & 1) * (GST * 2);
        #pragma unroll
        for (int ks = 0; ks < 32; ks += 16) {
            unsigned afh[4][4], afl[4][4], bfh[4][2], bfl[4][2];
            #pragma unroll
            for (int mt = 0; mt < 4; mt++) {
                unsigned off = (unsigned)((a_r + mt*16) * LDT + ks + a_c) * 2;
                ldsm4(afh[mt], sb + off);
                ldsm4(afl[mt], sb + oAl + off);
            }
            #pragma unroll
            for (int nt = 0; nt < 4; nt++) {
                unsigned off = (unsigned)((b_r + nt*8) * LDT + ks + b_c) * 2;
                ldsm2(bfh[nt], sb + oBh + off);
                ldsm2(bfl[nt], sb + oBl + off);
            }
            #pragma unroll
            for (int mt = 0; mt < 4; mt++)
                #pragma unroll
                for (int nt = 0; nt < 4; nt++) {
                    mma_bf16(acc[mt][nt], afh[mt], bfh[nt]);
                    mma_bf16(acc[mt][nt], afh[mt], bfl[nt]);
                    mma_bf16(acc[mt][nt], afl[mt], bfh[nt]);
                }
        }
        __syncthreads();
    }
}

// Kernel 1: projections.  z: 0=q(+bq)->f_q, 1=k->f_k, 2=v->f_v, 3=g(sigmoid)->g_g fp32
__global__ __launch_bounds__(256)
void proj_mma(const float* __restrict__ bq)
{
    const __nv_bfloat16 *Ah, *Al, *Bh, *Bl;
    __nv_bfloat16 *OH = nullptr, *OL = nullptr;
    const float* bias = nullptr;
    switch (blockIdx.z) {
        case 0:  Ah=b_s_h; Al=b_s_l; Bh=b_Wq_h; Bl=b_Wq_l; OH=f_q_h; OL=f_q_l; bias=bq; break;
        case 1:  Ah=b_k_h; Al=b_k_l; Bh=b_Wk_h; Bl=b_Wk_l; OH=f_k_h; OL=f_k_l; break;
        case 2:  Ah=b_k_h; Al=b_k_l; Bh=b_Wv_h; Bl=b_Wv_l; OH=f_v_h; OL=f_v_l; break;
        default: Ah=b_s_h; Al=b_s_l; Bh=b_Wg_h; Bl=b_Wg_l; break;
    }
    const int m0 = blockIdx.y * 128, n0 = blockIdx.x * 128;
    float acc[4][4][4];
    mma_core(Ah, Al, Bh, Bl, m0, n0, acc);

    const int lane = threadIdx.x & 31, warp = threadIdx.x >> 5;
    const int wm = warp >> 2, wn = warp & 3;
    const int lr = lane >> 2, lc = (lane & 3) * 2;
    #pragma unroll
    for (int mt = 0; mt < 4; mt++)
        #pragma unroll
        for (int nt = 0; nt < 4; nt++) {
            int row = m0 + wm*64 + mt*16 + lr;
            int col = n0 + wn*32 + nt*8 + lc;
            float v0 = acc[mt][nt][0], v1 = acc[mt][nt][1];
            float v2 = acc[mt][nt][2], v3 = acc[mt][nt][3];
            if (bias) { float b0_ = bias[col], b1_ = bias[col+1];
                        v0 += b0_; v1 += b1_; v2 += b0_; v3 += b1_; }
            if (blockIdx.z == 3) {
                v0 = 1.0f/(1.0f+__expf(-v0)); v1 = 1.0f/(1.0f+__expf(-v1));
                v2 = 1.0f/(1.0f+__expf(-v2)); v3 = 1.0f/(1.0f+__expf(-v3));
                *(float2*)&g_g[(size_t)row*CS + col]     = make_float2(v0, v1);
                *(float2*)&g_g[(size_t)(row+8)*CS + col] = make_float2(v2, v3);
            } else {
                split2_store(v0, v1, OH + (size_t)row*CS + col,     OL + (size_t)row*CS + col);
                split2_store(v2, v3, OH + (size_t)(row+8)*CS + col, OL + (size_t)(row+8)*CS + col);
            }
        }
}

// Kernel 6: out = (g*o) @ Wo^T
__global__ __launch_bounds__(256)
void out_mma(float* __restrict__ out)
{
    const int m0 = blockIdx.y * 128, n0 = blockIdx.x * 128;
    float acc[4][4][4];
    mma_core(b_a_h, b_a_l, b_Wo_h, b_Wo_l, m0, n0, acc);

    const int lane = threadIdx.x & 31, warp = threadIdx.x >> 5;
    const int wm = warp >> 2, wn = warp & 3;
    const int lr = lane >> 2, lc = (lane & 3) * 2;
    #pragma unroll
    for (int mt = 0; mt < 4; mt++)
        #pragma unroll
        for (int nt = 0; nt < 4; nt++) {
            int row = m0 + wm*64 + mt*16 + lr;
            int col = n0 + wn*32 + nt*8 + lc;
            *(float2*)&out[(size_t)row*CS + col]     = make_float2(acc[mt][nt][0], acc[mt][nt][1]);
            *(float2*)&out[(size_t)(row+8)*CS + col] = make_float2(acc[mt][nt][2], acc[mt][nt][3]);
        }
}

// ---------------- zbias (unchanged, verified) ----------------
__global__ __launch_bounds__(256)
void zbias_kernel(const float* __restrict__ bias, const float* __restrict__ mask)
{
    __shared__ float sb[256][33];
    const int tid = threadIdx.x;
    const long p0 = (long)blockIdx.x * 256;

    float acc[16];
    #pragma unroll
    for (int h = 0; h < 16; h++) acc[h] = 0.f;

    for (int cb = 0; cb < 4; cb++) {
        __syncthreads();
        #pragma unroll
        for (int r = 0; r < 8; r++) {
            int f = tid + r * 256;
            int pair = f >> 3, cq = f & 7;
            float4 v = *(const float4*)&bias[(p0 + pair) * 128 + cb * 32 + cq * 4];
            sb[pair][cq*4+0] = v.x; sb[pair][cq*4+1] = v.y;
            sb[pair][cq*4+2] = v.z; sb[pair][cq*4+3] = v.w;
        }
        __syncthreads();
        #pragma unroll
        for (int c = 0; c < 32; c++) {
            float bvf = sb[tid][c];
            int cg = cb * 32 + c;
            #pragma unroll
            for (int h = 0; h < 16; h++)
                acc[h] += bvf * cWz[cg * 16 + h];
        }
    }
    const long p = p0 + tid;
    const int j = (int)(p & (SEQ - 1));
    const float madd = (1.0f - mask[j]) * (-1000000.0f);
    #pragma unroll
    for (int h = 0; h < 16; h++)
        g_z[((long)h << 20) + p] = acc[h] + madd;
}

// ---------------- flash attention v2 ----------------
// 64-row q tiles, grid (16,16)=256 blocks, 512 threads = 16 warps:
// wm = warp>>2 (4 row-groups of 16), wj = warp&3 (4 j-quarters of 32).
// Each warp runs an independent online softmax over its 32-j slice of every
// 128-j tile; partials merged once at the end through smem. k/v 2-stage cp.async.
#define BI 64
#define LQ 72
#define KVST (4 * 128 * LQ)                       // halves per kv stage
#define FSMEM ((2*BI*LQ + 2*KVST) * 2)            // bytes

__global__ __launch_bounds__(512)
void flash_kernel()
{
    extern __shared__ __nv_bfloat16 fsm[];
    __nv_bfloat16* sqh = fsm;
    __nv_bfloat16* sql = sqh + BI*LQ;
    __nv_bfloat16* kvb = sql + BI*LQ;     // [stage][kh, kl, vh, vl] each 128*LQ
    float* cO = (float*)kvb;              // end-of-loop combine overlay

    __shared__ float cm[4][4][16];
    __shared__ float cl[4][4][16];

    const int h  = blockIdx.y;
    const int i0 = blockIdx.x * BI;
    const int tid  = threadIdx.x;
    const int lane = tid & 31;
    const int warp = tid >> 5;
    const int wm = warp >> 2, wj = warp & 3;
    const int lr = lane >> 2, t4 = lane & 3;

    // q tile: 64 x 64 hi/lo; 512 slots per array, 1 each
    {
        int r = tid >> 3, cc = (tid & 7) * 8;
        *(uint4*)&sqh[r*LQ + cc] = *(const uint4*)&f_q_h[(size_t)(i0+r)*CS + h*HD + cc];
        *(uint4*)&sql[r*LQ + cc] = *(const uint4*)&f_q_l[(size_t)(i0+r)*CS + h*HD + cc];
    }

    const unsigned uq  = smem_u32(sqh);
    const unsigned uql = smem_u32(sql);
    const unsigned ukv = smem_u32(kvb);
    const unsigned oKl = 128*LQ*2, oVh = 2*128*LQ*2, oVl = 3*128*LQ*2;

    const unsigned qoff = (unsigned)((wm*16 + (lane & 15)) * LQ + (lane >> 4) * 8) * 2;
    const unsigned koff = (unsigned)((wj*32 + (lane & 7)) * LQ + ((lane >> 3) & 1) * 8) * 2;
    const unsigned voff = (unsigned)((wj*32 + (lane & 7) + ((lane >> 3) & 1) * 8) * LQ) * 2;

    // kv async load: 1024 slots per array / 512 threads = 2 each, 4 arrays
    const int kr0 = tid >> 3,           kc = (tid & 7) * 8;
    const int kr1 = (tid + 512) >> 3;

    float m0 = -FINF, m1 = -FINF, l0 = 0.f, l1 = 0.f;
    float oac[8][4];
    #pragma unroll
    for (int d = 0; d < 8; d++)
        #pragma unroll
        for (int u = 0; u < 4; u++) oac[d][u] = 0.f;

    const float* Zbase = g_z + ((long)h << 20)
                       + (long)(i0 + wm*16 + lr) * SEQ + wj*32 + t4*2;

    // prologue: stage 0 = tile 0
    {
        unsigned sb = ukv;
        size_t g0 = (size_t)kr0 * CS + h*HD + kc, g1 = (size_t)kr1 * CS + h*HD + kc;
        unsigned s0 = (unsigned)(kr0*LQ + kc)*2, s1 = (unsigned)(kr1*LQ + kc)*2;
        cp16(sb + s0,       f_k_h + g0); cp16(sb + s1,       f_k_h + g1);
        cp16(sb + oKl + s0, f_k_l + g0); cp16(sb + oKl + s1, f_k_l + g1);
        cp16(sb + oVh + s0, f_v_h + g0); cp16(sb + oVh + s1, f_v_h + g1);
        cp16(sb + oVl + s0, f_v_l + g0); cp16(sb + oVl + s1, f_v_l + g1);
        cp_commit();
    }

    for (int jt = 0; jt < 8; jt++) {
        if (jt + 1 < 8) {
            unsigned sb = ukv + ((jt + 1) & 1) * (KVST * 2);
            size_t base = (size_t)((jt + 1) * 128) * CS + h*HD;
            size_t g0 = base + (size_t)kr0 * CS + kc, g1 = base + (size_t)kr1 * CS + kc;
            unsigned s0 = (unsigned)(kr0*LQ + kc)*2, s1 = (unsigned)(kr1*LQ + kc)*2;
            cp16(sb + s0,       f_k_h + g0); cp16(sb + s1,       f_k_h + g1);
            cp16(sb + oKl + s0, f_k_l + g0); cp16(sb + oKl + s1, f_k_l + g1);
            cp16(sb + oVh + s0, f_v_h + g0); cp16(sb + oVh + s1, f_v_h + g1);
            cp16(sb + oVl + s0, f_v_l + g0); cp16(sb + oVl + s1, f_v_l + g1);
            cp_commit();
            cp_wait1();
        } else {
            cp_wait0();
        }
        __syncthreads();

        const unsigned sb = ukv + (jt & 1) * (KVST * 2);

        // ---- S = q·k^T over warp's 16 x 32 slice (bf16x3) ----
        float sa[4][4];
        #pragma unroll
        for (int nt = 0; nt < 4; nt++)
            #pragma unroll
            for (int u = 0; u < 4; u++) sa[nt][u] = 0.f;

        #pragma unroll
        for (int ks = 0; ks < 64; ks += 16) {
            unsigned ah[4], al[4];
            ldsm4(ah, uq  + qoff + ks*2);
            ldsm4(al, uql + qoff + ks*2);
            #pragma unroll
            for (int nt = 0; nt < 4; nt++) {
                unsigned bh[2], bl[2];
                unsigned off = koff + (unsigned)(nt*8*LQ + ks) * 2;
                ldsm2(bh, sb + off);
                ldsm2(bl, sb + oKl + off);
                mma_bf16(sa[nt], ah, bh);
                mma_bf16(sa[nt], ah, bl);
                mma_bf16(sa[nt], al, bh);
            }
        }

        // ---- scale + z, online softmax (per warp, over its 32 j) ----
        const float* Zt = Zbase + jt * 128;
        float mx0 = -FINF, mx1 = -FINF;
        #pragma unroll
        for (int nt = 0; nt < 4; nt++) {
            float2 z0 = *(const float2*)(Zt + nt*8);
            float2 z1 = *(const float2*)(Zt + 8*SEQ + nt*8);
            sa[nt][0] = sa[nt][0]*0.125f + z0.x;
            sa[nt][1] = sa[nt][1]*0.125f + z0.y;
            sa[nt][2] = sa[nt][2]*0.125f + z1.x;
            sa[nt][3] = sa[nt][3]*0.125f + z1.y;
            mx0 = fmaxf(mx0, fmaxf(sa[nt][0], sa[nt][1]));
            mx1 = fmaxf(mx1, fmaxf(sa[nt][2], sa[nt][3]));
        }
        mx0 = fmaxf(mx0, __shfl_xor_sync(0xffffffffu, mx0, 1));
        mx0 = fmaxf(mx0, __shfl_xor_sync(0xffffffffu, mx0, 2));
        mx1 = fmaxf(mx1, __shfl_xor_sync(0xffffffffu, mx1, 1));
        mx1 = fmaxf(mx1, __shfl_xor_sync(0xffffffffu, mx1, 2));

        float mn0 = fmaxf(m0, mx0), mn1 = fmaxf(m1, mx1);
        float fa0 = __expf(m0 - mn0), fa1 = __expf(m1 - mn1);
        m0 = mn0; m1 = mn1;

        float sum0 = 0.f, sum1 = 0.f;
        #pragma unroll
        for (int nt = 0; nt < 4; nt++) {
            sa[nt][0] = __expf(sa[nt][0] - mn0);
            sa[nt][1] = __expf(sa[nt][1] - mn0);
            sa[nt][2] = __expf(sa[nt][2] - mn1);
            sa[nt][3] = __expf(sa[nt][3] - mn1);
            sum0 += sa[nt][0] + sa[nt][1];
            sum1 += sa[nt][2] + sa[nt][3];
        }
        sum0 += __shfl_xor_sync(0xffffffffu, sum0, 1);
        sum0 += __shfl_xor_sync(0xffffffffu, sum0, 2);
        sum1 += __shfl_xor_sync(0xffffffffu, sum1, 1);
        sum1 += __shfl_xor_sync(0xffffffffu, sum1, 2);
        l0 = l0 * fa0 + sum0;
        l1 = l1 * fa1 + sum1;

        #pragma unroll
        for (int d = 0; d < 8; d++) {
            oac[d][0] *= fa0; oac[d][1] *= fa0;
            oac[d][2] *= fa1; oac[d][3] *= fa1;
        }

        // ---- O += P·V over warp's 32 j (bf16x3) ----
        #pragma unroll
        for (int kt = 0; kt < 2; kt++) {
            float p00 = sa[2*kt][0],   p01 = sa[2*kt][1];
            float p02 = sa[2*kt][2],   p03 = sa[2*kt][3];
            float p10 = sa[2*kt+1][0], p11 = sa[2*kt+1][1];
            float p12 = sa[2*kt+1][2], p13 = sa[2*kt+1][3];

            unsigned pah[4], pal[4];
            pah[0] = packbf(p00, p01); pah[1] = packbf(p02, p03);
            pah[2] = packbf(p10, p11); pah[3] = packbf(p12, p13);
            {
                __nv_bfloat162 t0 = *(__nv_bfloat162*)&pah[0];
                __nv_bfloat162 t1 = *(__nv_bfloat162*)&pah[1];
                __nv_bfloat162 t2 = *(__nv_bfloat162*)&pah[2];
                __nv_bfloat162 t3 = *(__nv_bfloat162*)&pah[3];
                pal[0] = packbf(p00 - __bfloat162float(t0.x), p01 - __bfloat162float(t0.y));
                pal[1] = packbf(p02 - __bfloat162float(t1.x), p03 - __bfloat162float(t1.y));
                pal[2] = packbf(p10 - __bfloat162float(t2.x), p11 - __bfloat162float(t2.y));
                pal[3] = packbf(p12 - __bfloat162float(t3.x), p13 - __bfloat162float(t3.y));
            }

            #pragma unroll
            for (int dnt = 0; dnt < 8; dnt++) {
                unsigned bh[2], bl[2];
                unsigned off = voff + (unsigned)(kt*16*LQ + dnt*8) * 2;
                ldsm2t(bh, sb + oVh + off);
                ldsm2t(bl, sb + oVl + off);
                mma_bf16(oac[dnt], pah, bh);
                mma_bf16(oac[dnt], pah, bl);
                mma_bf16(oac[dnt], pal, bh);
            }
        }
        __syncthreads();
    }

    // ---- merge the 4 j-quarter partials via smem (overlaid on kv region) ----
    {
        float* myO = cO + (size_t)((wm*4 + wj) * 16) * 68;
        #pragma unroll
        for (int dnt = 0; dnt < 8; dnt++) {
            int c = dnt*8 + t4*2;
            myO[lr*68 + c]       = oac[dnt][0];
            myO[lr*68 + c + 1]   = oac[dnt][1];
            myO[(lr+8)*68 + c]   = oac[dnt][2];
            myO[(lr+8)*68 + c+1] = oac[dnt][3];
        }
        if (t4 == 0) {
            cm[wm][wj][lr] = m0;   cl[wm][wj][lr] = l0;
            cm[wm][wj][lr+8] = m1; cl[wm][wj][lr+8] = l1;
        }
    }
    __syncthreads();

    // warp (wm, wj) now combines rows of group wm, d-cols [wj*16, wj*16+16)
    {
        const int row = lane >> 1;
        const int db  = wj*16 + (lane & 1) * 8;
        float e[4], M = -FINF;
        #pragma unroll
        for (int w = 0; w < 4; w++) M = fmaxf(M, cm[wm][w][row]);
        float L = 0.f;
        #pragma unroll
        for (int w = 0; w < 4; w++) {
            e[w] = __expf(cm[wm][w][row] - M);
            L += cl[wm][w][row] * e[w];
        }
        const float invL = 1.0f / L;
        const int grow = i0 + wm*16 + row;
        const size_t gbase = (size_t)grow * CS + h*HD;

        #pragma unroll
        for (int p = 0; p < 4; p++) {
            int d = db + p*2;
            float o0 = 0.f, o1 = 0.f;
            #pragma unroll
            for (int w = 0; w < 4; w++) {
                const float* src = cO + (size_t)((wm*4 + w) * 16 + row) * 68 + d;
                o0 += src[0] * e[w];
                o1 += src[1] * e[w];
            }
            float2 gv = *(const float2*)&g_g[gbase + d];
            split2_store(o0 * invL * gv.x, o1 * invL * gv.y,
                         b_a_h + gbase + d, b_a_l + gbase + d);
        }
    }
}

// =====================================================================
extern "C" void kernel_launch(void* const* d_in, const int* in_sizes, int n_in,
                              void* d_out, int out_size)
{
    const float* s    = (const float*)d_in[0];
    const float* kin  = (const float*)d_in[1];
    const float* mask = (const float*)d_in[2];
    const float* bias = (const float*)d_in[3];
    const float* Wq   = (const float*)d_in[4];
    const float* bq   = (const float*)d_in[5];
    const float* Wk   = (const float*)d_in[6];
    const float* Wv   = (const float*)d_in[7];
    const float* Wg   = (const float*)d_in[8];
    const float* Wo   = (const float*)d_in[9];
    const float* Wz   = (const float*)d_in[10];
    float* out = (float*)d_out;

    cudaFuncSetAttribute(flash_kernel,
                         cudaFuncAttributeMaxDynamicSharedMemorySize, FSMEM);
    cudaFuncSetAttribute(proj_mma,
                         cudaFuncAttributeMaxDynamicSharedMemorySize, GSMEM);
    cudaFuncSetAttribute(out_mma,
                         cudaFuncAttributeMaxDynamicSharedMemorySize, GSMEM);

    cudaMemcpyToSymbolAsync(cWz, Wz, 128 * 16 * sizeof(float), 0,
                            cudaMemcpyDeviceToDevice);

    split_kernel<<<dim3(1024, 7), 256>>>(s, kin, Wq, Wk, Wv, Wg, Wo);
    proj_mma    <<<dim3(8, 8, 4),  256, GSMEM>>>(bq);
    zbias_kernel<<<4096,           256>>>(bias, mask);
    flash_kernel<<<dim3(16, 16),   512, FSMEM>>>();
    out_mma     <<<dim3(8, 8),     256, GSMEM>>>(out);
}